// round 1
// baseline (speedup 1.0000x reference)
#include <cuda_runtime.h>
#include <math.h>

// Problem constants
constexpr int Bc  = 32;
constexpr int Nc  = 512;
constexpr int INc = 128;
constexpr int Dc  = 256;
constexpr int Hc  = 8;
constexpr int Lc  = 2;
constexpr int Rc  = 10;
constexpr int FFc = 2048;
constexpr int Vc  = 10;
constexpr int DHc = 32;   // D / H
constexpr int Mc  = Bc * Nc; // 16384 rows

// -------- scratch (device globals; no runtime allocation allowed) ----------
__device__ float g_hA[Mc * Dc];
__device__ float g_hB[Mc * Dc];
__device__ float g_q[Mc * Dc];
__device__ float g_k[Mc * Dc];
__device__ float g_v[Mc * Dc];
__device__ float g_msg[Mc * Dc];
__device__ float g_t[Mc * Dc];
__device__ float g_qkv[Mc * 3 * Dc];
__device__ float g_ff[(size_t)Mc * FFc];

// ---------------------------------------------------------------------------
// Generic SGEMM: C[M x Ncols] = A[M x K] @ B[K x Ncols] + bias (+ReLU) (+res)
// TYPED variant: per-row weight/bias selection by node_types[row % Nc].
// Tile 64x64x16, 256 threads, 4x4 micro-tile.
// ---------------------------------------------------------------------------
template <bool TYPED>
__global__ __launch_bounds__(256)
void gemm_kernel(const float* __restrict__ A, int K, int Ncols,
                 const float* __restrict__ B0, const float* __restrict__ B1,
                 const float* __restrict__ bias0, const float* __restrict__ bias1,
                 const int* __restrict__ types,
                 const float* __restrict__ res,
                 float* __restrict__ C,
                 int do_relu)
{
    constexpr int BM = 64, BN = 64, BK = 16;
    __shared__ float As[BK][BM + 4];               // +4 keeps 16B alignment per row
    __shared__ float Bs0[BK][BN];
    __shared__ float Bs1[TYPED ? BK : 1][BN];

    const int tid = threadIdx.x;
    const int tx = tid & 15;         // 0..15 -> col group
    const int ty = tid >> 4;         // 0..15 -> row group
    const int m0 = blockIdx.y * BM;
    const int n0 = blockIdx.x * BN;

    float acc[4][4] = {};
    int rtype[4] = {0, 0, 0, 0};
    if (TYPED) {
#pragma unroll
        for (int i = 0; i < 4; i++)
            rtype[i] = types[(m0 + ty * 4 + i) % Nc];
    }

    for (int k0 = 0; k0 < K; k0 += BK) {
        // Load A tile (BM x BK), store transposed
#pragma unroll
        for (int i = 0; i < 4; i++) {
            int idx = tid + 256 * i;          // 0..1023
            int r = idx >> 4, c = idx & 15;
            As[c][r] = A[(size_t)(m0 + r) * K + (k0 + c)];
        }
        // Load B tile(s) (BK x BN)
#pragma unroll
        for (int i = 0; i < 4; i++) {
            int idx = tid + 256 * i;
            int r = idx >> 6, c = idx & 63;
            int n = n0 + c;
            float v0 = (n < Ncols) ? B0[(size_t)(k0 + r) * Ncols + n] : 0.f;
            Bs0[r][c] = v0;
            if (TYPED) {
                float v1 = (n < Ncols) ? B1[(size_t)(k0 + r) * Ncols + n] : 0.f;
                Bs1[r][c] = v1;
            }
        }
        __syncthreads();

#pragma unroll
        for (int k = 0; k < BK; k++) {
            float4 a4 = *reinterpret_cast<const float4*>(&As[k][ty * 4]);
            float4 b04 = *reinterpret_cast<const float4*>(&Bs0[k][tx * 4]);
            float a[4] = {a4.x, a4.y, a4.z, a4.w};
            float b0v[4] = {b04.x, b04.y, b04.z, b04.w};
            float b1v[4];
            if (TYPED) {
                float4 b14 = *reinterpret_cast<const float4*>(&Bs1[k][tx * 4]);
                b1v[0] = b14.x; b1v[1] = b14.y; b1v[2] = b14.z; b1v[3] = b14.w;
            }
#pragma unroll
            for (int i = 0; i < 4; i++) {
#pragma unroll
                for (int j = 0; j < 4; j++) {
                    float bv = b0v[j];
                    if (TYPED) bv = rtype[i] ? b1v[j] : b0v[j];
                    acc[i][j] += a[i] * bv;
                }
            }
        }
        __syncthreads();
    }

    // Epilogue: bias (+relu) (+residual)
#pragma unroll
    for (int i = 0; i < 4; i++) {
        int m = m0 + ty * 4 + i;
#pragma unroll
        for (int j = 0; j < 4; j++) {
            int n = n0 + tx * 4 + j;
            if (n < Ncols) {
                float bv;
                if (TYPED) bv = rtype[i] ? bias1[n] : bias0[n];
                else       bv = bias0[n];
                float v = acc[i][j] + bv;
                if (do_relu) v = fmaxf(v, 0.f);
                if (res) v += res[(size_t)m * Ncols + n];
                C[(size_t)m * Ncols + n] = v;
            }
        }
    }
}

// ---------------------------------------------------------------------------
// Fused attention: block handles (b, h, 16 query rows). Scores, optional
// relational bias, softmax, attn@V all in shared memory. N=512, DH=32.
// q/k/v are row-major with arbitrary row stride; head slice at h*DH.
// ---------------------------------------------------------------------------
constexpr int AROWS = 16;
__global__ __launch_bounds__(256)
void attn_kernel(const float* __restrict__ qb, int qstride,
                 const float* __restrict__ kb, int kstride,
                 const float* __restrict__ vb, int vstride,
                 float* __restrict__ out,             // (B*N, D)
                 const float* __restrict__ relp,      // [R, H] for this layer, or null
                 const int* __restrict__ rel_ids)     // (B, N)
{
    __shared__ float sS[AROWS][Nc];        // 32 KB
    __shared__ float sQ[AROWS][DHc];       // 2 KB
    __shared__ float sKV[64][DHc + 1];     // 8.25 KB
    const int b = blockIdx.z, h = blockIdx.y;
    const int n0 = blockIdx.x * AROWS;
    const int t = threadIdx.x;

    // Load Q rows (scaled by 1/sqrt(DH))
#pragma unroll
    for (int i = 0; i < 2; i++) {
        int idx = t + 256 * i;                 // 0..511
        int r = idx >> 5, d = idx & 31;
        sQ[r][d] = qb[(size_t)(b * Nc + n0 + r) * qstride + h * DHc + d]
                   * 0.17677669529663687f;    // 1/sqrt(32)
    }
    __syncthreads();

    // Scores
    for (int m0 = 0; m0 < Nc; m0 += 64) {
#pragma unroll
        for (int i = 0; i < 8; i++) {
            int idx = t + 256 * i;             // 0..2047
            int mm = idx >> 5, d = idx & 31;
            sKV[mm][d] = kb[(size_t)(b * Nc + m0 + mm) * kstride + h * DHc + d];
        }
        __syncthreads();
#pragma unroll
        for (int p = 0; p < 4; p++) {
            int idx = p * 256 + t;             // 0..1023 = 16 rows x 64 keys
            int r = idx >> 6, mm = idx & 63;
            float s = 0.f;
#pragma unroll
            for (int d = 0; d < DHc; d++) s += sQ[r][d] * sKV[mm][d];
            if (relp) s += relp[rel_ids[b * Nc + m0 + mm] * Hc + h];
            sS[r][m0 + mm] = s;
        }
        __syncthreads();
    }

    // Softmax: 16 threads per row, each covering 32 strided columns
    {
        int r = t >> 4, g = t & 15;
        float mx = -1e30f;
#pragma unroll
        for (int i = 0; i < 32; i++) mx = fmaxf(mx, sS[r][g + 16 * i]);
#pragma unroll
        for (int o = 8; o >= 1; o >>= 1) mx = fmaxf(mx, __shfl_xor_sync(0xffffffffu, mx, o));
        float sum = 0.f;
#pragma unroll
        for (int i = 0; i < 32; i++) {
            float e = __expf(sS[r][g + 16 * i] - mx);
            sS[r][g + 16 * i] = e;
            sum += e;
        }
#pragma unroll
        for (int o = 8; o >= 1; o >>= 1) sum += __shfl_xor_sync(0xffffffffu, sum, o);
        float inv = 1.f / sum;
#pragma unroll
        for (int i = 0; i < 32; i++) sS[r][g + 16 * i] *= inv;
    }
    __syncthreads();

    // attn @ V
    float acc[2] = {0.f, 0.f};
    for (int m0 = 0; m0 < Nc; m0 += 64) {
#pragma unroll
        for (int i = 0; i < 8; i++) {
            int idx = t + 256 * i;
            int mm = idx >> 5, d = idx & 31;
            sKV[mm][d] = vb[(size_t)(b * Nc + m0 + mm) * vstride + h * DHc + d];
        }
        __syncthreads();
#pragma unroll
        for (int p = 0; p < 2; p++) {
            int idx = p * 256 + t;             // 16 rows x 32 dims
            int r = idx >> 5, d = idx & 31;
            float a = acc[p];
#pragma unroll
            for (int mm = 0; mm < 64; mm++) a += sS[r][m0 + mm] * sKV[mm][d];
            acc[p] = a;
        }
        __syncthreads();
    }
#pragma unroll
    for (int p = 0; p < 2; p++) {
        int idx = p * 256 + t;
        int r = idx >> 5, d = idx & 31;
        out[(size_t)(b * Nc + n0 + r) * Dc + h * DHc + d] = acc[p];
    }
}

// ---------------------------------------------------------------------------
// LayerNorm over D=256, one block per row, 256 threads
// ---------------------------------------------------------------------------
__global__ __launch_bounds__(256)
void ln_kernel(const float* __restrict__ x, const float* __restrict__ gg,
               const float* __restrict__ bb, float* __restrict__ out)
{
    int row = blockIdx.x;
    int t = threadIdx.x;
    float v = x[(size_t)row * Dc + t];
    __shared__ float red[8];

    float s = v;
#pragma unroll
    for (int o = 16; o >= 1; o >>= 1) s += __shfl_xor_sync(0xffffffffu, s, o);
    if ((t & 31) == 0) red[t >> 5] = s;
    __syncthreads();
    float tot = 0.f;
#pragma unroll
    for (int i = 0; i < 8; i++) tot += red[i];
    float mean = tot * (1.f / 256.f);
    __syncthreads();

    float d = v - mean;
    s = d * d;
#pragma unroll
    for (int o = 16; o >= 1; o >>= 1) s += __shfl_xor_sync(0xffffffffu, s, o);
    if ((t & 31) == 0) red[t >> 5] = s;
    __syncthreads();
    tot = 0.f;
#pragma unroll
    for (int i = 0; i < 8; i++) tot += red[i];
    float var = tot * (1.f / 256.f);

    out[(size_t)row * Dc + t] = d * rsqrtf(var + 1e-5f) * gg[t] + bb[t];
}

// GELU (tanh approximation — JAX default)
__global__ __launch_bounds__(256)
void gelu_kernel(float* __restrict__ x, int n)
{
    int i = blockIdx.x * blockDim.x + threadIdx.x;
    if (i < n) {
        float v = x[i];
        float c = 0.7978845608028654f * (v + 0.044715f * v * v * v);
        x[i] = 0.5f * v * (1.f + tanhf(c));
    }
}

__global__ __launch_bounds__(256)
void copy_kernel(const float* __restrict__ src, float* __restrict__ dst, int n)
{
    int i = blockIdx.x * blockDim.x + threadIdx.x;
    if (i < n) dst[i] = src[i];
}

// ---------------------------------------------------------------------------
// Host orchestration
// ---------------------------------------------------------------------------
extern "C" void kernel_launch(void* const* d_in, const int* in_sizes, int n_in,
                              void* d_out, int out_size)
{
    (void)in_sizes; (void)n_in; (void)out_size;

    const float* x        = (const float*)d_in[0];
    const int*   types    = (const int*)  d_in[1];
    const int*   rel_ids  = (const int*)  d_in[2];
    const float* W_in     = (const float*)d_in[3];
    const float* b_in     = (const float*)d_in[4];
    const float* Wq       = (const float*)d_in[5];
    const float* Wk       = (const float*)d_in[6];
    const float* Wv       = (const float*)d_in[7];
    const float* Wo       = (const float*)d_in[8];
    const float* bq       = (const float*)d_in[9];
    const float* bk       = (const float*)d_in[10];
    const float* bv       = (const float*)d_in[11];
    const float* bo       = (const float*)d_in[12];
    const float* relp     = (const float*)d_in[13];
    const float* Wqkv     = (const float*)d_in[14];
    const float* bqkv     = (const float*)d_in[15];
    const float* Wot      = (const float*)d_in[16];
    const float* bot      = (const float*)d_in[17];
    const float* ln1_g    = (const float*)d_in[18];
    const float* ln1_b    = (const float*)d_in[19];
    const float* ln2_g    = (const float*)d_in[20];
    const float* ln2_b    = (const float*)d_in[21];
    const float* Wf1      = (const float*)d_in[22];
    const float* bf1      = (const float*)d_in[23];
    const float* Wf2      = (const float*)d_in[24];
    const float* bf2      = (const float*)d_in[25];
    const float* Wc       = (const float*)d_in[26];
    const float* bc       = (const float*)d_in[27];
    float* out = (float*)d_out;

    float *hA, *hB, *qb, *kb, *vb, *msg, *tb, *qkv, *ff;
    cudaGetSymbolAddress((void**)&hA,  g_hA);
    cudaGetSymbolAddress((void**)&hB,  g_hB);
    cudaGetSymbolAddress((void**)&qb,  g_q);
    cudaGetSymbolAddress((void**)&kb,  g_k);
    cudaGetSymbolAddress((void**)&vb,  g_v);
    cudaGetSymbolAddress((void**)&msg, g_msg);
    cudaGetSymbolAddress((void**)&tb,  g_t);
    cudaGetSymbolAddress((void**)&qkv, g_qkv);
    cudaGetSymbolAddress((void**)&ff,  g_ff);

    const dim3 thr(256);
    auto grid_gemm = [](int ncols) { return dim3((ncols + 63) / 64, Mc / 64); };

    // h = x @ W_in + b_in
    gemm_kernel<false><<<grid_gemm(Dc), thr>>>(
        x, INc, Dc, W_in, nullptr, b_in, nullptr, nullptr, nullptr, hA, 0);

    float* hcur = hA;
    float* hnext = hB;

    for (int l = 0; l < Lc; l++) {
        const float* Wq0 = Wq + (size_t)(l * 2 + 0) * Dc * Dc;
        const float* Wq1 = Wq + (size_t)(l * 2 + 1) * Dc * Dc;
        const float* Wk0 = Wk + (size_t)(l * 2 + 0) * Dc * Dc;
        const float* Wk1 = Wk + (size_t)(l * 2 + 1) * Dc * Dc;
        const float* Wv0 = Wv + (size_t)(l * 2 + 0) * Dc * Dc;
        const float* Wv1 = Wv + (size_t)(l * 2 + 1) * Dc * Dc;
        const float* Wo0 = Wo + (size_t)(l * 2 + 0) * Dc * Dc;
        const float* Wo1 = Wo + (size_t)(l * 2 + 1) * Dc * Dc;
        const float* bq0 = bq + (size_t)(l * 2 + 0) * Dc;
        const float* bq1 = bq + (size_t)(l * 2 + 1) * Dc;
        const float* bk0 = bk + (size_t)(l * 2 + 0) * Dc;
        const float* bk1 = bk + (size_t)(l * 2 + 1) * Dc;
        const float* bv0 = bv + (size_t)(l * 2 + 0) * Dc;
        const float* bv1 = bv + (size_t)(l * 2 + 1) * Dc;
        const float* bo0 = bo + (size_t)(l * 2 + 0) * Dc;
        const float* bo1 = bo + (size_t)(l * 2 + 1) * Dc;

        gemm_kernel<true><<<grid_gemm(Dc), thr>>>(
            hcur, Dc, Dc, Wq0, Wq1, bq0, bq1, types, nullptr, qb, 0);
        gemm_kernel<true><<<grid_gemm(Dc), thr>>>(
            hcur, Dc, Dc, Wk0, Wk1, bk0, bk1, types, nullptr, kb, 0);
        gemm_kernel<true><<<grid_gemm(Dc), thr>>>(
            hcur, Dc, Dc, Wv0, Wv1, bv0, bv1, types, nullptr, vb, 0);

        attn_kernel<<<dim3(Nc / AROWS, Hc, Bc), thr>>>(
            qb, Dc, kb, Dc, vb, Dc, msg, relp + (size_t)l * Rc * Hc, rel_ids);

        gelu_kernel<<<(Mc * Dc + 255) / 256, thr>>>(msg, Mc * Dc);

        gemm_kernel<true><<<grid_gemm(Dc), thr>>>(
            msg, Dc, Dc, Wo0, Wo1, bo0, bo1, types, hcur, hnext, 0);

        float* tmp = hcur; hcur = hnext; hnext = tmp;
    }

    // Encoder
    gemm_kernel<false><<<grid_gemm(3 * Dc), thr>>>(
        hcur, Dc, 3 * Dc, Wqkv, nullptr, bqkv, nullptr, nullptr, nullptr, qkv, 0);

    attn_kernel<<<dim3(Nc / AROWS, Hc, Bc), thr>>>(
        qkv, 3 * Dc, qkv + Dc, 3 * Dc, qkv + 2 * Dc, 3 * Dc, msg, nullptr, nullptr);

    gemm_kernel<false><<<grid_gemm(Dc), thr>>>(
        msg, Dc, Dc, Wot, nullptr, bot, nullptr, nullptr, hcur, tb, 0);

    ln_kernel<<<Mc, thr>>>(tb, ln1_g, ln1_b, hnext);

    gemm_kernel<false><<<grid_gemm(FFc), thr>>>(
        hnext, Dc, FFc, Wf1, nullptr, bf1, nullptr, nullptr, nullptr, ff, 1);

    gemm_kernel<false><<<grid_gemm(Dc), thr>>>(
        ff, FFc, Dc, Wf2, nullptr, bf2, nullptr, nullptr, hnext, tb, 0);

    ln_kernel<<<Mc, thr>>>(tb, ln2_g, ln2_b, hcur);   // final h

    // logits -> front of d_out; h -> after logits
    gemm_kernel<false><<<grid_gemm(Vc), thr>>>(
        hcur, Dc, Vc, Wc, nullptr, bc, nullptr, nullptr, nullptr, out, 0);

    copy_kernel<<<(Mc * Dc + 255) / 256, thr>>>(hcur, out + (size_t)Mc * Vc, Mc * Dc);
}

// round 2
// speedup vs baseline: 1.4552x; 1.4552x over previous
#include <cuda_runtime.h>
#include <math.h>

// Problem constants
constexpr int Bc  = 32;
constexpr int Nc  = 512;
constexpr int INc = 128;
constexpr int Dc  = 256;
constexpr int Hc  = 8;
constexpr int Lc  = 2;
constexpr int Rc  = 10;
constexpr int FFc = 2048;
constexpr int Vc  = 10;
constexpr int Mc  = Bc * Nc;        // 16384 rows
constexpr int MPAD = Mc + 256;      // 16640 = 130 * 128 (padded permuted rows)
constexpr int QS  = 3 * Dc;         // 768, packed qkv row stride

// -------- scratch (device globals; no runtime allocation allowed) ----------
__device__ float g_hA[Mc * Dc];
__device__ float g_hB[Mc * Dc];
__device__ float g_qkv[Mc * QS];
__device__ float g_msg[Mc * Dc];
__device__ float g_t[Mc * Dc];
__device__ float g_ff[(size_t)Mc * FFc];
__device__ float g_wt[2 * Dc * QS];   // packed typed QKV weights for one layer
__device__ float g_bt[2 * QS];        // packed typed QKV bias
__device__ int   g_perm[MPAD];
__device__ int   g_meta[4];

// ---------------------------------------------------------------------------
// setup_perm: partition row space by node type. type depends only on n.
// Layout: [ type0 rows | pad(-1) to 128 | type1 rows | pad(-1) to MPAD ].
// meta[0] = start of type-1 region (multiple of 128).
// ---------------------------------------------------------------------------
__global__ void setup_perm(const int* __restrict__ types,
                           int* __restrict__ perm, int* __restrict__ meta)
{
    __shared__ int s[Nc];
    int n = threadIdx.x;                 // 512 threads
    int tp = types[n];
    s[n] = (tp == 0) ? 1 : 0;
    __syncthreads();
    // Hillis-Steele inclusive scan
    for (int off = 1; off < Nc; off <<= 1) {
        int v = s[n];
        int add = (n >= off) ? s[n - off] : 0;
        __syncthreads();
        s[n] = v + add;
        __syncthreads();
    }
    int count0 = s[Nc - 1];
    int rank = (tp == 0) ? (s[n] - 1) : (n - s[n]);
    int rows0  = count0 * Bc;
    int rows0p = (rows0 + 127) & ~127;
    int base = (tp == 0) ? rank * Bc : rows0p + rank * Bc;
    for (int b = 0; b < Bc; b++)
        perm[base + b] = b * Nc + n;
    if (n == 0) meta[0] = rows0p;
    __syncthreads();
    int rows1 = (Nc - count0) * Bc;
    int total = rows0p + rows1;
    for (int i = n; i < MPAD; i += Nc)
        if ((i >= rows0 && i < rows0p) || i >= total) perm[i] = -1;
}

// ---------------------------------------------------------------------------
// SGEMM: C[M x N] = A[M x K] @ B[K x N] + bias (+relu) (+res)
// 128x128x16 tile, 256 threads, 8x8 micro-tile, reg-prefetch.
// If perm != null: rows gathered/scattered via perm; per-tile type from meta[0]
// selects B0/B1 + bias0/bias1 (tiles never straddle the type boundary).
// ---------------------------------------------------------------------------
__global__ __launch_bounds__(256, 2)
void gemm2(const float* __restrict__ A, int K, int N,
           const float* __restrict__ B0, const float* __restrict__ B1,
           const float* __restrict__ bias0, const float* __restrict__ bias1,
           const int* __restrict__ perm, const int* __restrict__ meta,
           const float* __restrict__ res, float* __restrict__ C,
           int do_relu)
{
    __shared__ float As[16][132];
    __shared__ float Bs[16][128];

    const int t  = threadIdx.x;
    const int tx = t & 15;
    const int ty = t >> 4;
    const int m0 = blockIdx.y * 128;
    const int n0 = blockIdx.x * 128;
    const bool typed = (perm != nullptr);

    const float* B = B0;
    const float* bias = bias0;
    if (typed && m0 >= meta[0]) { B = B1; bias = bias1; }

    // A loader rows (2 per thread)
    const float* pA[2];
#pragma unroll
    for (int i = 0; i < 2; i++) {
        int idx = t + 256 * i;
        int r = idx >> 2, c4 = idx & 3;
        int grow = typed ? perm[m0 + r] : (m0 + r);
        if (grow < 0) grow = 0;
        pA[i] = A + (size_t)grow * K + c4 * 4;
    }
    // B loader ptrs (2 per thread)
    const float* pB[2];
#pragma unroll
    for (int i = 0; i < 2; i++) {
        int idx = t + 256 * i;
        int c = idx >> 5, j4 = idx & 31;
        pB[i] = B + (size_t)c * N + n0 + j4 * 4;
    }

    float acc[8][8] = {};
    float4 ra[2], rb[2];

    const int KT = K >> 4;
    // prologue: stage 0
#pragma unroll
    for (int i = 0; i < 2; i++) {
        ra[i] = *reinterpret_cast<const float4*>(pA[i]);
        rb[i] = *reinterpret_cast<const float4*>(pB[i]);
    }
#pragma unroll
    for (int i = 0; i < 2; i++) {
        int idx = t + 256 * i;
        int r = idx >> 2, c4 = idx & 3;
        As[c4 * 4 + 0][r] = ra[i].x;
        As[c4 * 4 + 1][r] = ra[i].y;
        As[c4 * 4 + 2][r] = ra[i].z;
        As[c4 * 4 + 3][r] = ra[i].w;
        int c = idx >> 5, j4 = idx & 31;
        *reinterpret_cast<float4*>(&Bs[c][j4 * 4]) = rb[i];
    }
    __syncthreads();

    for (int kt = 0; kt < KT; kt++) {
        if (kt + 1 < KT) {
            int ko = (kt + 1) * 16;
#pragma unroll
            for (int i = 0; i < 2; i++) {
                ra[i] = *reinterpret_cast<const float4*>(pA[i] + ko);
                int idx = t + 256 * i;
                int c = idx >> 5;
                rb[i] = *reinterpret_cast<const float4*>(pB[i] + (size_t)ko * N + 0 * c);
            }
        }
#pragma unroll
        for (int k = 0; k < 16; k++) {
            float4 a0 = *reinterpret_cast<const float4*>(&As[k][ty * 8]);
            float4 a1 = *reinterpret_cast<const float4*>(&As[k][ty * 8 + 4]);
            float4 b0 = *reinterpret_cast<const float4*>(&Bs[k][tx * 8]);
            float4 b1 = *reinterpret_cast<const float4*>(&Bs[k][tx * 8 + 4]);
            float ar[8] = {a0.x, a0.y, a0.z, a0.w, a1.x, a1.y, a1.z, a1.w};
            float br[8] = {b0.x, b0.y, b0.z, b0.w, b1.x, b1.y, b1.z, b1.w};
#pragma unroll
            for (int i = 0; i < 8; i++)
#pragma unroll
                for (int j = 0; j < 8; j++)
                    acc[i][j] += ar[i] * br[j];
        }
        __syncthreads();
        if (kt + 1 < KT) {
#pragma unroll
            for (int i = 0; i < 2; i++) {
                int idx = t + 256 * i;
                int r = idx >> 2, c4 = idx & 3;
                As[c4 * 4 + 0][r] = ra[i].x;
                As[c4 * 4 + 1][r] = ra[i].y;
                As[c4 * 4 + 2][r] = ra[i].z;
                As[c4 * 4 + 3][r] = ra[i].w;
                int c = idx >> 5, j4 = idx & 31;
                *reinterpret_cast<float4*>(&Bs[c][j4 * 4]) = rb[i];
            }
            __syncthreads();
        }
    }

    // epilogue
    int nb = n0 + tx * 8;
    float4 bb0 = *reinterpret_cast<const float4*>(&bias[nb]);
    float4 bb1 = *reinterpret_cast<const float4*>(&bias[nb + 4]);
#pragma unroll
    for (int i = 0; i < 8; i++) {
        int mrow = m0 + ty * 8 + i;
        int grow = typed ? perm[mrow] : mrow;
        if (grow < 0) continue;
        float4 v0, v1;
        v0.x = acc[i][0] + bb0.x; v0.y = acc[i][1] + bb0.y;
        v0.z = acc[i][2] + bb0.z; v0.w = acc[i][3] + bb0.w;
        v1.x = acc[i][4] + bb1.x; v1.y = acc[i][5] + bb1.y;
        v1.z = acc[i][6] + bb1.z; v1.w = acc[i][7] + bb1.w;
        if (do_relu) {
            v0.x = fmaxf(v0.x, 0.f); v0.y = fmaxf(v0.y, 0.f);
            v0.z = fmaxf(v0.z, 0.f); v0.w = fmaxf(v0.w, 0.f);
            v1.x = fmaxf(v1.x, 0.f); v1.y = fmaxf(v1.y, 0.f);
            v1.z = fmaxf(v1.z, 0.f); v1.w = fmaxf(v1.w, 0.f);
        }
        if (res) {
            float4 r0 = *reinterpret_cast<const float4*>(&res[(size_t)grow * N + nb]);
            float4 r1 = *reinterpret_cast<const float4*>(&res[(size_t)grow * N + nb + 4]);
            v0.x += r0.x; v0.y += r0.y; v0.z += r0.z; v0.w += r0.w;
            v1.x += r1.x; v1.y += r1.y; v1.z += r1.z; v1.w += r1.w;
        }
        *reinterpret_cast<float4*>(&C[(size_t)grow * N + nb])     = v0;
        *reinterpret_cast<float4*>(&C[(size_t)grow * N + nb + 4]) = v1;
    }
}

// ---------------------------------------------------------------------------
// pack typed QKV weights/bias for layer l into g_wt/g_bt
// ---------------------------------------------------------------------------
__global__ void pack_w(const float* __restrict__ Wq, const float* __restrict__ Wk,
                       const float* __restrict__ Wv, int l, float* __restrict__ out)
{
    int idx = blockIdx.x * 256 + threadIdx.x;     // 2*256*768
    if (idx >= 2 * Dc * QS) return;
    int t2 = idx / (Dc * QS);
    int rem = idx % (Dc * QS);
    int k = rem / QS, j = rem % QS;
    const float* src = (j < Dc) ? Wq : ((j < 2 * Dc) ? Wk : Wv);
    int jj = j & (Dc - 1);
    out[idx] = src[(((size_t)l * 2 + t2) * Dc + k) * Dc + jj];
}
__global__ void pack_b(const float* __restrict__ bq, const float* __restrict__ bk,
                       const float* __restrict__ bv, int l, float* __restrict__ out)
{
    int idx = blockIdx.x * 256 + threadIdx.x;     // 2*768
    if (idx >= 2 * QS) return;
    int t2 = idx / QS, j = idx % QS;
    const float* src = (j < Dc) ? bq : ((j < 2 * Dc) ? bk : bv);
    int jj = j & (Dc - 1);
    out[idx] = src[((size_t)l * 2 + t2) * Dc + jj];
}

// ---------------------------------------------------------------------------
// Fused attention v2: block = (b, h, 32 query rows). qkv packed, stride 768.
// Register-microtiled scores (4x4) and AV (1x4-vec). Optional rel bias and
// fused gelu on output.
// ---------------------------------------------------------------------------
constexpr int AR = 32;  // rows per block
constexpr int SP = 520; // sS row pitch
__global__ __launch_bounds__(256)
void attn2(const float* __restrict__ qkv, float* __restrict__ outbuf,
           const float* __restrict__ relp, const int* __restrict__ rel_ids,
           int do_gelu)
{
    extern __shared__ float sm[];
    float* sS    = sm;                       // 32 * 520
    float* sQt   = sS + AR * SP;             // [32 d][36]: transposed Q
    float* sKV   = sQt + 32 * 36;            // K: [128][33] / V: [128][36]
    float* sBias = sKV + 128 * 36;           // 512

    const int b = blockIdx.z, h = blockIdx.y;
    const int n0 = blockIdx.x * AR;
    const int t = threadIdx.x;

    // ---- stage Q transposed (scaled) ----
    {
        int r = t >> 3, dq = t & 7;
        const float* qp = qkv + (size_t)(b * Nc + n0 + r) * QS + h * 32 + dq * 4;
        float4 q4 = *reinterpret_cast<const float4*>(qp);
        const float sc = 0.17677669529663687f; // 1/sqrt(32)
        sQt[(dq * 4 + 0) * 36 + r] = q4.x * sc;
        sQt[(dq * 4 + 1) * 36 + r] = q4.y * sc;
        sQt[(dq * 4 + 2) * 36 + r] = q4.z * sc;
        sQt[(dq * 4 + 3) * 36 + r] = q4.w * sc;
    }
    // ---- stage rel bias (per key) ----
#pragma unroll
    for (int i = 0; i < 2; i++) {
        int mm = t + 256 * i;
        sBias[mm] = relp ? relp[rel_ids[b * Nc + mm] * Hc + h] : 0.f;
    }
    __syncthreads();

    // ---- scores: S[r][mm] = Q[r]·K[mm] ----
    const int rg = t >> 5;     // 8 row groups of 4
    const int mg = t & 31;     // key lane
    for (int c0 = 0; c0 < Nc; c0 += 128) {
        // stage K chunk [128][33]
#pragma unroll
        for (int i = 0; i < 4; i++) {
            int idx = t + 256 * i;
            int mm = idx >> 3, dq = idx & 7;
            const float* kp = qkv + (size_t)(b * Nc + c0 + mm) * QS + Dc + h * 32 + dq * 4;
            float4 kv = *reinterpret_cast<const float4*>(kp);
            sKV[mm * 33 + dq * 4 + 0] = kv.x;
            sKV[mm * 33 + dq * 4 + 1] = kv.y;
            sKV[mm * 33 + dq * 4 + 2] = kv.z;
            sKV[mm * 33 + dq * 4 + 3] = kv.w;
        }
        __syncthreads();
        float acc[4][4] = {};
#pragma unroll
        for (int d = 0; d < 32; d++) {
            float4 qv = *reinterpret_cast<const float4*>(&sQt[d * 36 + rg * 4]);
            float k0 = sKV[(mg +  0) * 33 + d];
            float k1 = sKV[(mg + 32) * 33 + d];
            float k2 = sKV[(mg + 64) * 33 + d];
            float k3 = sKV[(mg + 96) * 33 + d];
            float qr[4] = {qv.x, qv.y, qv.z, qv.w};
            float kr[4] = {k0, k1, k2, k3};
#pragma unroll
            for (int i = 0; i < 4; i++)
#pragma unroll
                for (int u = 0; u < 4; u++)
                    acc[i][u] += qr[i] * kr[u];
        }
#pragma unroll
        for (int i = 0; i < 4; i++)
#pragma unroll
            for (int u = 0; u < 4; u++)
                sS[(rg * 4 + i) * SP + c0 + mg + 32 * u] = acc[i][u];
        __syncthreads();
    }

    // ---- softmax (bias added here): 8 threads per row ----
    {
        int r = t >> 3, l8 = t & 7;
        float mx = -1e30f;
#pragma unroll
        for (int i = 0; i < 64; i++) {
            int c = l8 + 8 * i;
            float v = sS[r * SP + c] + sBias[c];
            sS[r * SP + c] = v;
            mx = fmaxf(mx, v);
        }
        mx = fmaxf(mx, __shfl_xor_sync(0xffffffffu, mx, 1));
        mx = fmaxf(mx, __shfl_xor_sync(0xffffffffu, mx, 2));
        mx = fmaxf(mx, __shfl_xor_sync(0xffffffffu, mx, 4));
        float sum = 0.f;
#pragma unroll
        for (int i = 0; i < 64; i++) {
            int c = l8 + 8 * i;
            float e = __expf(sS[r * SP + c] - mx);
            sS[r * SP + c] = e;
            sum += e;
        }
        sum += __shfl_xor_sync(0xffffffffu, sum, 1);
        sum += __shfl_xor_sync(0xffffffffu, sum, 2);
        sum += __shfl_xor_sync(0xffffffffu, sum, 4);
        float inv = 1.f / sum;
#pragma unroll
        for (int i = 0; i < 64; i++)
            sS[r * SP + l8 + 8 * i] *= inv;
    }
    __syncthreads();

    // ---- AV: out[r][d] = sum_mm S[r][mm] * V[mm][d] ----
    {
        int r = t >> 3, dg = t & 7;
        float4 acc4 = {0.f, 0.f, 0.f, 0.f};
        for (int c0 = 0; c0 < Nc; c0 += 128) {
#pragma unroll
            for (int i = 0; i < 4; i++) {
                int idx = t + 256 * i;
                int mm = idx >> 3, dq = idx & 7;
                const float* vp = qkv + (size_t)(b * Nc + c0 + mm) * QS + 2 * Dc + h * 32 + dq * 4;
                *reinterpret_cast<float4*>(&sKV[mm * 36 + dq * 4]) =
                    *reinterpret_cast<const float4*>(vp);
            }
            __syncthreads();
#pragma unroll 4
            for (int mm = 0; mm < 128; mm++) {
                float s = sS[r * SP + c0 + mm];
                float4 v = *reinterpret_cast<const float4*>(&sKV[mm * 36 + dg * 4]);
                acc4.x += s * v.x; acc4.y += s * v.y;
                acc4.z += s * v.z; acc4.w += s * v.w;
            }
            __syncthreads();
        }
        if (do_gelu) {
            float vv[4] = {acc4.x, acc4.y, acc4.z, acc4.w};
#pragma unroll
            for (int i = 0; i < 4; i++) {
                float v = vv[i];
                float c = 0.7978845608028654f * (v + 0.044715f * v * v * v);
                vv[i] = 0.5f * v * (1.f + tanhf(c));
            }
            acc4.x = vv[0]; acc4.y = vv[1]; acc4.z = vv[2]; acc4.w = vv[3];
        }
        float* op = outbuf + (size_t)(b * Nc + n0 + r) * Dc + h * 32 + dg * 4;
        *reinterpret_cast<float4*>(op) = acc4;
    }
}

// ---------------------------------------------------------------------------
// LayerNorm over D=256, one block per row
// ---------------------------------------------------------------------------
__global__ __launch_bounds__(256)
void ln_kernel(const float* __restrict__ x, const float* __restrict__ gg,
               const float* __restrict__ bb, float* __restrict__ out)
{
    int row = blockIdx.x;
    int t = threadIdx.x;
    float v = x[(size_t)row * Dc + t];
    __shared__ float red[8];

    float s = v;
#pragma unroll
    for (int o = 16; o >= 1; o >>= 1) s += __shfl_xor_sync(0xffffffffu, s, o);
    if ((t & 31) == 0) red[t >> 5] = s;
    __syncthreads();
    float tot = 0.f;
#pragma unroll
    for (int i = 0; i < 8; i++) tot += red[i];
    float mean = tot * (1.f / 256.f);
    __syncthreads();

    float d = v - mean;
    s = d * d;
#pragma unroll
    for (int o = 16; o >= 1; o >>= 1) s += __shfl_xor_sync(0xffffffffu, s, o);
    if ((t & 31) == 0) red[t >> 5] = s;
    __syncthreads();
    tot = 0.f;
#pragma unroll
    for (int i = 0; i < 8; i++) tot += red[i];
    float var = tot * (1.f / 256.f);

    out[(size_t)row * Dc + t] = d * rsqrtf(var + 1e-5f) * gg[t] + bb[t];
}

// ---------------------------------------------------------------------------
// Classifier: warp per row, K=256, V=10
// ---------------------------------------------------------------------------
__global__ __launch_bounds__(256)
void cls_kernel(const float* __restrict__ h, const float* __restrict__ Wc,
                const float* __restrict__ bc, float* __restrict__ out)
{
    __shared__ float sW[Dc * Vc];
    __shared__ float sb[Vc];
    int t = threadIdx.x;
#pragma unroll
    for (int i = 0; i < 10; i++) {
        int idx = t + 256 * i;
        if (idx < Dc * Vc) sW[idx] = Wc[idx];
    }
    if (t < Vc) sb[t] = bc[t];
    __syncthreads();

    int wid = t >> 5, lane = t & 31;
    int row = blockIdx.x * 8 + wid;
    float hv[8];
#pragma unroll
    for (int j = 0; j < 8; j++) hv[j] = h[(size_t)row * Dc + lane + 32 * j];

    float sums[Vc];
#pragma unroll
    for (int v = 0; v < Vc; v++) {
        float p = 0.f;
#pragma unroll
        for (int j = 0; j < 8; j++) p += hv[j] * sW[(lane + 32 * j) * Vc + v];
#pragma unroll
        for (int o = 16; o >= 1; o >>= 1) p += __shfl_xor_sync(0xffffffffu, p, o);
        sums[v] = p;
    }
    if (lane == 0) {
#pragma unroll
        for (int v = 0; v < Vc; v++) out[(size_t)row * Vc + v] = sums[v] + sb[v];
    }
}

// ---------------------------------------------------------------------------
// Host orchestration
// ---------------------------------------------------------------------------
extern "C" void kernel_launch(void* const* d_in, const int* in_sizes, int n_in,
                              void* d_out, int out_size)
{
    (void)in_sizes; (void)n_in; (void)out_size;

    const float* x     = (const float*)d_in[0];
    const int*   types = (const int*)  d_in[1];
    const int*   rel   = (const int*)  d_in[2];
    const float* W_in  = (const float*)d_in[3];
    const float* b_in  = (const float*)d_in[4];
    const float* Wq    = (const float*)d_in[5];
    const float* Wk    = (const float*)d_in[6];
    const float* Wv    = (const float*)d_in[7];
    const float* Wo    = (const float*)d_in[8];
    const float* bq    = (const float*)d_in[9];
    const float* bk    = (const float*)d_in[10];
    const float* bv    = (const float*)d_in[11];
    const float* bo    = (const float*)d_in[12];
    const float* relp  = (const float*)d_in[13];
    const float* Wqkv  = (const float*)d_in[14];
    const float* bqkv  = (const float*)d_in[15];
    const float* Wot   = (const float*)d_in[16];
    const float* bot   = (const float*)d_in[17];
    const float* ln1_g = (const float*)d_in[18];
    const float* ln1_b = (const float*)d_in[19];
    const float* ln2_g = (const float*)d_in[20];
    const float* ln2_b = (const float*)d_in[21];
    const float* Wf1   = (const float*)d_in[22];
    const float* bf1   = (const float*)d_in[23];
    const float* Wf2   = (const float*)d_in[24];
    const float* bf2   = (const float*)d_in[25];
    const float* Wc    = (const float*)d_in[26];
    const float* bc    = (const float*)d_in[27];
    float* out = (float*)d_out;

    float *hA, *hB, *qkv, *msg, *tb, *ff, *wt, *bt;
    int *perm, *meta;
    cudaGetSymbolAddress((void**)&hA,   g_hA);
    cudaGetSymbolAddress((void**)&hB,   g_hB);
    cudaGetSymbolAddress((void**)&qkv,  g_qkv);
    cudaGetSymbolAddress((void**)&msg,  g_msg);
    cudaGetSymbolAddress((void**)&tb,   g_t);
    cudaGetSymbolAddress((void**)&ff,   g_ff);
    cudaGetSymbolAddress((void**)&wt,   g_wt);
    cudaGetSymbolAddress((void**)&bt,   g_bt);
    cudaGetSymbolAddress((void**)&perm, g_perm);
    cudaGetSymbolAddress((void**)&meta, g_meta);

    static bool attr_set = false;
    const int ATTN_SMEM = (AR * SP + 32 * 36 + 128 * 36 + Nc) * 4;
    if (!attr_set) {
        cudaFuncSetAttribute(attn2, cudaFuncAttributeMaxDynamicSharedMemorySize, ATTN_SMEM);
        attr_set = true;
    }

    const dim3 thr(256);

    setup_perm<<<1, Nc>>>(types, perm, meta);

    // h = x @ W_in + b_in
    gemm2<<<dim3(2, 128), thr>>>(x, INc, Dc, W_in, nullptr, b_in, nullptr,
                                 nullptr, nullptr, nullptr, hA, 0);

    float* hcur = hA;
    float* hnext = hB;

    for (int l = 0; l < Lc; l++) {
        pack_w<<<(2 * Dc * QS + 255) / 256, thr>>>(Wq, Wk, Wv, l, wt);
        pack_b<<<(2 * QS + 255) / 256, thr>>>(bq, bk, bv, l, bt);

        // typed QKV projection
        gemm2<<<dim3(6, 130), thr>>>(hcur, Dc, QS, wt, wt + Dc * QS,
                                     bt, bt + QS, perm, meta, nullptr, qkv, 0);

        attn2<<<dim3(Nc / AR, Hc, Bc), thr, ATTN_SMEM>>>(
            qkv, msg, relp + (size_t)l * Rc * Hc, rel, /*gelu=*/1);

        // typed output projection + residual
        const float* Wo0 = Wo + (size_t)(l * 2 + 0) * Dc * Dc;
        const float* Wo1 = Wo + (size_t)(l * 2 + 1) * Dc * Dc;
        const float* bo0 = bo + (size_t)(l * 2 + 0) * Dc;
        const float* bo1 = bo + (size_t)(l * 2 + 1) * Dc;
        gemm2<<<dim3(2, 130), thr>>>(msg, Dc, Dc, Wo0, Wo1, bo0, bo1,
                                     perm, meta, hcur, hnext, 0);
        float* tmp = hcur; hcur = hnext; hnext = tmp;
    }

    // encoder
    gemm2<<<dim3(6, 128), thr>>>(hcur, Dc, QS, Wqkv, nullptr, bqkv, nullptr,
                                 nullptr, nullptr, nullptr, qkv, 0);

    attn2<<<dim3(Nc / AR, Hc, Bc), thr, ATTN_SMEM>>>(
        qkv, msg, nullptr, nullptr, /*gelu=*/0);

    gemm2<<<dim3(2, 128), thr>>>(msg, Dc, Dc, Wot, nullptr, bot, nullptr,
                                 nullptr, nullptr, hcur, tb, 0);

    ln_kernel<<<Mc, thr>>>(tb, ln1_g, ln1_b, hnext);

    gemm2<<<dim3(16, 128), thr>>>(hnext, Dc, FFc, Wf1, nullptr, bf1, nullptr,
                                  nullptr, nullptr, nullptr, ff, 1);

    gemm2<<<dim3(2, 128), thr>>>(ff, FFc, Dc, Wf2, nullptr, bf2, nullptr,
                                 nullptr, nullptr, hnext, tb, 0);

    // final h -> directly into d_out after logits
    float* hfin = out + (size_t)Mc * Vc;
    ln_kernel<<<Mc, thr>>>(tb, ln2_g, ln2_b, hfin);

    cls_kernel<<<Mc / 8, thr>>>(hfin, Wc, bc, out);
}

// round 4
// speedup vs baseline: 1.8055x; 1.2407x over previous
#include <cuda_runtime.h>
#include <cuda_bf16.h>
#include <cstdint>
#include <math.h>

// Problem constants
constexpr int Bc  = 32;
constexpr int Nc  = 512;
constexpr int INc = 128;
constexpr int Dc  = 256;
constexpr int Hc  = 8;
constexpr int Lc  = 2;
constexpr int Rc  = 10;
constexpr int FFc = 2048;
constexpr int Vc  = 10;
constexpr int Mc  = Bc * Nc;        // 16384
constexpr int MPAD = Mc + 256;      // 16640 = 130*128
constexpr int QS  = 3 * Dc;         // 768

// -------- scratch (device globals) ----------
__device__ float g_hA[Mc * Dc];
__device__ float g_hB[Mc * Dc];
__device__ float g_qkv[Mc * QS];
__device__ float g_t[Mc * Dc];
__device__ float g_wt[2 * Dc * QS];
__device__ float g_bt[2 * QS];
__device__ int   g_perm[MPAD];
__device__ int   g_meta[4];
// bf16 hi/lo activation splits
__device__ __nv_bfloat16 g_xs[2][Mc * INc];
__device__ __nv_bfloat16 g_hsA[2][Mc * Dc];
__device__ __nv_bfloat16 g_hsB[2][Mc * Dc];
__device__ __nv_bfloat16 g_msgs[2][Mc * Dc];
__device__ __nv_bfloat16 g_ffs[2][(size_t)Mc * FFc];
__device__ __nv_bfloat16 g_lns[2][Mc * Dc];
// bf16 hi/lo transposed weights [N][K]
__device__ __nv_bfloat16 g_binT[2][Dc * INc];
__device__ __nv_bfloat16 g_qkvT[2][2][QS * Dc];   // [type][hi/lo]
__device__ __nv_bfloat16 g_woT[2][2][Dc * Dc];
__device__ __nv_bfloat16 g_encT[2][QS * Dc];
__device__ __nv_bfloat16 g_wotT[2][Dc * Dc];
__device__ __nv_bfloat16 g_f1T[2][FFc * Dc];
__device__ __nv_bfloat16 g_f2T[2][Dc * FFc];

// ---------------------------------------------------------------------------
// helpers
// ---------------------------------------------------------------------------
__device__ __forceinline__ uint32_t smem_u32(const void* p) {
    uint32_t a;
    asm("{ .reg .u64 t; cvta.to.shared.u64 t, %1; cvt.u32.u64 %0, t; }"
        : "=r"(a) : "l"(p));
    return a;
}
#define SWZ128(o) ((o) ^ (((o) >> 3) & 0x70))

#define CP_A16(sm, gm) \
    asm volatile("cp.async.cg.shared.global [%0], [%1], 16;" :: "r"(sm), "l"(gm))
#define CP_COMMIT() asm volatile("cp.async.commit_group;" ::: "memory")
#define CP_WAIT1()  asm volatile("cp.async.wait_group 1;" ::: "memory")
#define CP_WAIT0()  asm volatile("cp.async.wait_group 0;" ::: "memory")

#define LDSM4(r, addr) \
    asm volatile("ldmatrix.sync.aligned.m8n8.x4.shared.b16 {%0,%1,%2,%3}, [%4];" \
        : "=r"((r)[0]), "=r"((r)[1]), "=r"((r)[2]), "=r"((r)[3]) : "r"(addr))

#define MMA16816(d, a, b0_, b1_) \
    asm volatile("mma.sync.aligned.m16n8k16.row.col.f32.bf16.bf16.f32 " \
        "{%0,%1,%2,%3}, {%4,%5,%6,%7}, {%8,%9}, {%0,%1,%2,%3};" \
        : "+f"((d)[0]), "+f"((d)[1]), "+f"((d)[2]), "+f"((d)[3]) \
        : "r"((a)[0]), "r"((a)[1]), "r"((a)[2]), "r"((a)[3]), "r"(b0_), "r"(b1_))

__device__ __forceinline__ void split_bf(float v, __nv_bfloat16& h, __nv_bfloat16& l) {
    h = __float2bfloat16(v);
    l = __float2bfloat16(v - __bfloat162float(h));
}

// ---------------------------------------------------------------------------
// setup_perm: partition rows by node type (from R2)
// ---------------------------------------------------------------------------
__global__ void setup_perm(const int* __restrict__ types,
                           int* __restrict__ perm, int* __restrict__ meta)
{
    __shared__ int s[Nc];
    int n = threadIdx.x;
    int tp = types[n];
    s[n] = (tp == 0) ? 1 : 0;
    __syncthreads();
    for (int off = 1; off < Nc; off <<= 1) {
        int v = s[n];
        int add = (n >= off) ? s[n - off] : 0;
        __syncthreads();
        s[n] = v + add;
        __syncthreads();
    }
    int count0 = s[Nc - 1];
    int rank = (tp == 0) ? (s[n] - 1) : (n - s[n]);
    int rows0  = count0 * Bc;
    int rows0p = (rows0 + 127) & ~127;
    int base = (tp == 0) ? rank * Bc : rows0p + rank * Bc;
    for (int b = 0; b < Bc; b++)
        perm[base + b] = b * Nc + n;
    if (n == 0) meta[0] = rows0p;
    __syncthreads();
    int rows1 = (Nc - count0) * Bc;
    int total = rows0p + rows1;
    for (int i = n; i < MPAD; i += Nc)
        if ((i >= rows0 && i < rows0p) || i >= total) perm[i] = -1;
}

// ---------------------------------------------------------------------------
// transpose + bf16-split: src fp32 [K][N] -> hi/lo bf16 [N][K]
// ---------------------------------------------------------------------------
__global__ __launch_bounds__(256)
void tsplit(const float* __restrict__ src, int K, int N,
            __nv_bfloat16* __restrict__ dhi, __nv_bfloat16* __restrict__ dlo)
{
    __shared__ float tile[32][33];
    int n0 = blockIdx.x * 32, k0 = blockIdx.y * 32;
    int tx = threadIdx.x & 31, ty = threadIdx.x >> 5;
#pragma unroll
    for (int i = 0; i < 4; i++)
        tile[ty + 8 * i][tx] = src[(size_t)(k0 + ty + 8 * i) * N + n0 + tx];
    __syncthreads();
#pragma unroll
    for (int i = 0; i < 4; i++) {
        int n = n0 + ty + 8 * i;
        int k = k0 + tx;
        float v = tile[tx][ty + 8 * i];
        __nv_bfloat16 h, l;
        split_bf(v, h, l);
        dhi[(size_t)n * K + k] = h;
        dlo[(size_t)n * K + k] = l;
    }
}

// elementwise fp32 -> bf16 hi/lo (for input x)
__global__ __launch_bounds__(256)
void fsplit(const float* __restrict__ src, __nv_bfloat16* __restrict__ hi,
            __nv_bfloat16* __restrict__ lo, int n)
{
    int i = blockIdx.x * 256 + threadIdx.x;
    if (i < n) {
        __nv_bfloat16 h, l;
        split_bf(src[i], h, l);
        hi[i] = h; lo[i] = l;
    }
}

// pack typed QKV weights/bias for layer l
__global__ void pack_w(const float* __restrict__ Wq, const float* __restrict__ Wk,
                       const float* __restrict__ Wv, int l, float* __restrict__ out)
{
    int idx = blockIdx.x * 256 + threadIdx.x;
    if (idx >= 2 * Dc * QS) return;
    int t2 = idx / (Dc * QS);
    int rem = idx % (Dc * QS);
    int k = rem / QS, j = rem % QS;
    const float* src = (j < Dc) ? Wq : ((j < 2 * Dc) ? Wk : Wv);
    int jj = j & (Dc - 1);
    out[idx] = src[(((size_t)l * 2 + t2) * Dc + k) * Dc + jj];
}
__global__ void pack_b(const float* __restrict__ bq, const float* __restrict__ bk,
                       const float* __restrict__ bv, int l, float* __restrict__ out)
{
    int idx = blockIdx.x * 256 + threadIdx.x;
    if (idx >= 2 * QS) return;
    int t2 = idx / QS, j = idx % QS;
    const float* src = (j < Dc) ? bq : ((j < 2 * Dc) ? bk : bv);
    int jj = j & (Dc - 1);
    out[idx] = src[((size_t)l * 2 + t2) * Dc + jj];
}

// ---------------------------------------------------------------------------
// bf16 mma.sync GEMM with 2-term split (K' = 3K):
//   slices: s0 = Ahi*Bhi, s1 = Alo*Bhi, s2 = Ahi*Blo
// Tile 128x128, chunk 64 bf16 (128B SW128 rows), double-buffered cp.async.
// 8 warps (2m x 4n), warp tile 64x32, mma.m16n8k16.
// Epilogue: smem bounce -> coalesced store with bias/relu/res/perm + bf16 split.
// ---------------------------------------------------------------------------
constexpr int STAGE_BYTES = 32768;           // A 16KB + B 16KB
constexpr int MMB_DYN = 132 * 130 * 4;       // >= 2*STAGE and bounce (128x130 f32)

__global__ __launch_bounds__(256)
void mm_bf(const __nv_bfloat16* __restrict__ Ahi, const __nv_bfloat16* __restrict__ Alo,
           int K, int N,
           const __nv_bfloat16* __restrict__ Bhi0, const __nv_bfloat16* __restrict__ Blo0,
           const __nv_bfloat16* __restrict__ Bhi1, const __nv_bfloat16* __restrict__ Blo1,
           const float* __restrict__ bias0, const float* __restrict__ bias1,
           const int* __restrict__ perm, const int* __restrict__ meta,
           const float* __restrict__ res, float* __restrict__ Cf,
           __nv_bfloat16* __restrict__ Chi, __nv_bfloat16* __restrict__ Clo,
           int do_relu)
{
    extern __shared__ char sb[];
    __shared__ int sPerm[128];

    const int t = threadIdx.x;
    const int m0 = blockIdx.y * 128, n0 = blockIdx.x * 128;
    const bool typed = (perm != nullptr);

    const __nv_bfloat16* Bhi = Bhi0;
    const __nv_bfloat16* Blo = Blo0;
    const float* bias = bias0;
    if (typed && m0 >= meta[0]) { Bhi = Bhi1; Blo = Blo1; bias = bias1; }

    if (t < 128) sPerm[t] = typed ? perm[m0 + t] : (m0 + t);
    __syncthreads();

    // loader setup: row lr handled by 2 threads (4 x 16B chunks each)
    const int lr = t >> 1;
    int ag = sPerm[lr]; if (ag < 0) ag = 0;
    const __nv_bfloat16* pAhi = Ahi + (size_t)ag * K;
    const __nv_bfloat16* pAlo = Alo + (size_t)ag * K;
    const __nv_bfloat16* pBhi = Bhi + (size_t)(n0 + lr) * K;
    const __nv_bfloat16* pBlo = Blo + (size_t)(n0 + lr) * K;
    const uint32_t sbase = smem_u32(sb);
    uint32_t offA[4];
#pragma unroll
    for (int i = 0; i < 4; i++) {
        int c = (t & 1) * 4 + i;
        offA[i] = SWZ128((uint32_t)(lr * 128 + c * 16));
    }
    const int S = 3 * K / 64;

    auto issue_load = [&](int kc, int stg) {
        int kp = kc * 64;
        int s = kp / K, k0 = kp - s * K;
        const __nv_bfloat16* pa = (s == 1) ? pAlo : pAhi;
        const __nv_bfloat16* pb = (s == 2) ? pBlo : pBhi;
        uint32_t so = sbase + stg * STAGE_BYTES;
#pragma unroll
        for (int i = 0; i < 4; i++) {
            int c = (t & 1) * 4 + i;
            CP_A16(so + offA[i], pa + k0 + c * 8);
            CP_A16(so + 16384 + offA[i], pb + k0 + c * 8);
        }
        CP_COMMIT();
    };

    float acc[4][4][4] = {};
    const int wid = t >> 5, lane = t & 31;
    const int wm = wid & 1, wn = wid >> 1;

    issue_load(0, 0);
    issue_load(1, 1);

    for (int kc = 0; kc < S; kc++) {
        if (kc + 1 < S) { CP_WAIT1(); } else { CP_WAIT0(); }
        __syncthreads();
        uint32_t sA = sbase + (kc & 1) * STAGE_BYTES;
        uint32_t sB = sA + 16384;
#pragma unroll
        for (int kk = 0; kk < 64; kk += 16) {
            uint32_t a[4][4], b[2][4];
#pragma unroll
            for (int mi = 0; mi < 4; mi++) {
                int row = wm * 64 + mi * 16 + (lane & 15);
                int kcol = kk + ((lane >> 4) << 3);
                LDSM4(a[mi], sA + SWZ128((uint32_t)(row * 128 + kcol * 2)));
            }
#pragma unroll
            for (int bj = 0; bj < 2; bj++) {
                int nrow = wn * 32 + bj * 16 + ((lane >> 4) & 1) * 8 + (lane & 7);
                int kcol = kk + ((lane >> 3) & 1) * 8;
                LDSM4(b[bj], sB + SWZ128((uint32_t)(nrow * 128 + kcol * 2)));
            }
#pragma unroll
            for (int mi = 0; mi < 4; mi++)
#pragma unroll
                for (int bj = 0; bj < 2; bj++) {
                    MMA16816(acc[mi][bj * 2],     a[mi], b[bj][0], b[bj][1]);
                    MMA16816(acc[mi][bj * 2 + 1], a[mi], b[bj][2], b[bj][3]);
                }
        }
        __syncthreads();
        if (kc + 2 < S) issue_load(kc + 2, kc & 1);
    }

    // bounce accumulators to smem (pitch 130 floats)
    float* Cs = (float*)sb;
#pragma unroll
    for (int mi = 0; mi < 4; mi++)
#pragma unroll
        for (int nj = 0; nj < 4; nj++) {
            int row = wm * 64 + mi * 16 + (lane >> 2);
            int col = wn * 32 + nj * 8 + (lane & 3) * 2;
            *reinterpret_cast<float2*>(&Cs[row * 130 + col]) =
                make_float2(acc[mi][nj][0], acc[mi][nj][1]);
            *reinterpret_cast<float2*>(&Cs[(row + 8) * 130 + col]) =
                make_float2(acc[mi][nj][2], acc[mi][nj][3]);
        }
    __syncthreads();

    // coalesced write-out
    {
        int col = t & 127, half = t >> 7;
        float bv = bias[n0 + col];
        for (int i = 0; i < 64; i++) {
            int r = half * 64 + i;
            int g = sPerm[r];
            if (g < 0) continue;
            float v = Cs[r * 130 + col] + bv;
            if (do_relu) v = fmaxf(v, 0.f);
            size_t o = (size_t)g * N + n0 + col;
            if (res) v += res[o];
            if (Cf) Cf[o] = v;
            if (Chi) {
                __nv_bfloat16 h, l;
                split_bf(v, h, l);
                Chi[o] = h; Clo[o] = l;
            }
        }
    }
}

// ---------------------------------------------------------------------------
// Fused attention (R2 core): writes bf16 hi/lo split of (gelu'd) output
// ---------------------------------------------------------------------------
constexpr int AR = 32;
constexpr int SP = 520;
__global__ __launch_bounds__(256)
void attn2(const float* __restrict__ qkv,
           __nv_bfloat16* __restrict__ outh, __nv_bfloat16* __restrict__ outl,
           const float* __restrict__ relp, const int* __restrict__ rel_ids,
           int do_gelu)
{
    extern __shared__ float sm[];
    float* sS    = sm;
    float* sQt   = sS + AR * SP;
    float* sKV   = sQt + 32 * 36;
    float* sBias = sKV + 128 * 36;

    const int b = blockIdx.z, h = blockIdx.y;
    const int n0 = blockIdx.x * AR;
    const int t = threadIdx.x;

    {
        int r = t >> 3, dq = t & 7;
        const float* qp = qkv + (size_t)(b * Nc + n0 + r) * QS + h * 32 + dq * 4;
        float4 q4 = *reinterpret_cast<const float4*>(qp);
        const float sc = 0.17677669529663687f;
        sQt[(dq * 4 + 0) * 36 + r] = q4.x * sc;
        sQt[(dq * 4 + 1) * 36 + r] = q4.y * sc;
        sQt[(dq * 4 + 2) * 36 + r] = q4.z * sc;
        sQt[(dq * 4 + 3) * 36 + r] = q4.w * sc;
    }
#pragma unroll
    for (int i = 0; i < 2; i++) {
        int mm = t + 256 * i;
        sBias[mm] = relp ? relp[rel_ids[b * Nc + mm] * Hc + h] : 0.f;
    }
    __syncthreads();

    const int rg = t >> 5;
    const int mg = t & 31;
    for (int c0 = 0; c0 < Nc; c0 += 128) {
#pragma unroll
        for (int i = 0; i < 4; i++) {
            int idx = t + 256 * i;
            int mm = idx >> 3, dq = idx & 7;
            const float* kp = qkv + (size_t)(b * Nc + c0 + mm) * QS + Dc + h * 32 + dq * 4;
            float4 kv = *reinterpret_cast<const float4*>(kp);
            sKV[mm * 33 + dq * 4 + 0] = kv.x;
            sKV[mm * 33 + dq * 4 + 1] = kv.y;
            sKV[mm * 33 + dq * 4 + 2] = kv.z;
            sKV[mm * 33 + dq * 4 + 3] = kv.w;
        }
        __syncthreads();
        float acc[4][4] = {};
#pragma unroll
        for (int d = 0; d < 32; d++) {
            float4 qv = *reinterpret_cast<const float4*>(&sQt[d * 36 + rg * 4]);
            float k0 = sKV[(mg +  0) * 33 + d];
            float k1 = sKV[(mg + 32) * 33 + d];
            float k2 = sKV[(mg + 64) * 33 + d];
            float k3 = sKV[(mg + 96) * 33 + d];
            float qr[4] = {qv.x, qv.y, qv.z, qv.w};
            float kr[4] = {k0, k1, k2, k3};
#pragma unroll
            for (int i = 0; i < 4; i++)
#pragma unroll
                for (int u = 0; u < 4; u++)
                    acc[i][u] += qr[i] * kr[u];
        }
#pragma unroll
        for (int i = 0; i < 4; i++)
#pragma unroll
            for (int u = 0; u < 4; u++)
                sS[(rg * 4 + i) * SP + c0 + mg + 32 * u] = acc[i][u];
        __syncthreads();
    }

    {
        int r = t >> 3, l8 = t & 7;
        float mx = -1e30f;
#pragma unroll
        for (int i = 0; i < 64; i++) {
            int c = l8 + 8 * i;
            float v = sS[r * SP + c] + sBias[c];
            sS[r * SP + c] = v;
            mx = fmaxf(mx, v);
        }
        mx = fmaxf(mx, __shfl_xor_sync(0xffffffffu, mx, 1));
        mx = fmaxf(mx, __shfl_xor_sync(0xffffffffu, mx, 2));
        mx = fmaxf(mx, __shfl_xor_sync(0xffffffffu, mx, 4));
        float sum = 0.f;
#pragma unroll
        for (int i = 0; i < 64; i++) {
            int c = l8 + 8 * i;
            float e = __expf(sS[r * SP + c] - mx);
            sS[r * SP + c] = e;
            sum += e;
        }
        sum += __shfl_xor_sync(0xffffffffu, sum, 1);
        sum += __shfl_xor_sync(0xffffffffu, sum, 2);
        sum += __shfl_xor_sync(0xffffffffu, sum, 4);
        float inv = 1.f / sum;
#pragma unroll
        for (int i = 0; i < 64; i++)
            sS[r * SP + l8 + 8 * i] *= inv;
    }
    __syncthreads();

    {
        int r = t >> 3, dg = t & 7;
        float4 acc4 = {0.f, 0.f, 0.f, 0.f};
        for (int c0 = 0; c0 < Nc; c0 += 128) {
#pragma unroll
            for (int i = 0; i < 4; i++) {
                int idx = t + 256 * i;
                int mm = idx >> 3, dq = idx & 7;
                const float* vp = qkv + (size_t)(b * Nc + c0 + mm) * QS + 2 * Dc + h * 32 + dq * 4;
                *reinterpret_cast<float4*>(&sKV[mm * 36 + dq * 4]) =
                    *reinterpret_cast<const float4*>(vp);
            }
            __syncthreads();
#pragma unroll 4
            for (int mm = 0; mm < 128; mm++) {
                float s = sS[r * SP + c0 + mm];
                float4 v = *reinterpret_cast<const float4*>(&sKV[mm * 36 + dg * 4]);
                acc4.x += s * v.x; acc4.y += s * v.y;
                acc4.z += s * v.z; acc4.w += s * v.w;
            }
            __syncthreads();
        }
        float vv[4] = {acc4.x, acc4.y, acc4.z, acc4.w};
        if (do_gelu) {
#pragma unroll
            for (int i = 0; i < 4; i++) {
                float v = vv[i];
                float c = 0.7978845608028654f * (v + 0.044715f * v * v * v);
                vv[i] = 0.5f * v * (1.f + tanhf(c));
            }
        }
        __nv_bfloat16 hv[4], lv[4];
#pragma unroll
        for (int i = 0; i < 4; i++) split_bf(vv[i], hv[i], lv[i]);
        size_t o = (size_t)(b * Nc + n0 + r) * Dc + h * 32 + dg * 4;
        *reinterpret_cast<ushort4*>(outh + o) = *reinterpret_cast<ushort4*>(hv);
        *reinterpret_cast<ushort4*>(outl + o) = *reinterpret_cast<ushort4*>(lv);
    }
}

// ---------------------------------------------------------------------------
// LayerNorm, optional bf16 split output
// ---------------------------------------------------------------------------
__global__ __launch_bounds__(256)
void ln_kernel(const float* __restrict__ x, const float* __restrict__ gg,
               const float* __restrict__ bb, float* __restrict__ out,
               __nv_bfloat16* __restrict__ ohi, __nv_bfloat16* __restrict__ olo)
{
    int row = blockIdx.x;
    int t = threadIdx.x;
    float v = x[(size_t)row * Dc + t];
    __shared__ float red[8];

    float s = v;
#pragma unroll
    for (int o = 16; o >= 1; o >>= 1) s += __shfl_xor_sync(0xffffffffu, s, o);
    if ((t & 31) == 0) red[t >> 5] = s;
    __syncthreads();
    float tot = 0.f;
#pragma unroll
    for (int i = 0; i < 8; i++) tot += red[i];
    float mean = tot * (1.f / 256.f);
    __syncthreads();

    float d = v - mean;
    s = d * d;
#pragma unroll
    for (int o = 16; o >= 1; o >>= 1) s += __shfl_xor_sync(0xffffffffu, s, o);
    if ((t & 31) == 0) red[t >> 5] = s;
    __syncthreads();
    tot = 0.f;
#pragma unroll
    for (int i = 0; i < 8; i++) tot += red[i];
    float var = tot * (1.f / 256.f);

    float r = d * rsqrtf(var + 1e-5f) * gg[t] + bb[t];
    out[(size_t)row * Dc + t] = r;
    if (ohi) {
        __nv_bfloat16 h, l;
        split_bf(r, h, l);
        ohi[(size_t)row * Dc + t] = h;
        olo[(size_t)row * Dc + t] = l;
    }
}

// ---------------------------------------------------------------------------
// Classifier (warp per row)
// ---------------------------------------------------------------------------
__global__ __launch_bounds__(256)
void cls_kernel(const float* __restrict__ h, const float* __restrict__ Wc,
                const float* __restrict__ bc, float* __restrict__ out)
{
    __shared__ float sW[Dc * Vc];
    __shared__ float sb[Vc];
    int t = threadIdx.x;
#pragma unroll
    for (int i = 0; i < 10; i++) {
        int idx = t + 256 * i;
        if (idx < Dc * Vc) sW[idx] = Wc[idx];
    }
    if (t < Vc) sb[t] = bc[t];
    __syncthreads();

    int wid = t >> 5, lane = t & 31;
    int row = blockIdx.x * 8 + wid;
    float hv[8];
#pragma unroll
    for (int j = 0; j < 8; j++) hv[j] = h[(size_t)row * Dc + lane + 32 * j];

    float sums[Vc];
#pragma unroll
    for (int v = 0; v < Vc; v++) {
        float p = 0.f;
#pragma unroll
        for (int j = 0; j < 8; j++) p += hv[j] * sW[(lane + 32 * j) * Vc + v];
#pragma unroll
        for (int o = 16; o >= 1; o >>= 1) p += __shfl_xor_sync(0xffffffffu, p, o);
        sums[v] = p;
    }
    if (lane == 0) {
#pragma unroll
        for (int v = 0; v < Vc; v++) out[(size_t)row * Vc + v] = sums[v] + sb[v];
    }
}

// ---------------------------------------------------------------------------
// Host orchestration
// ---------------------------------------------------------------------------
extern "C" void kernel_launch(void* const* d_in, const int* in_sizes, int n_in,
                              void* d_out, int out_size)
{
    (void)in_sizes; (void)n_in; (void)out_size;

    const float* x     = (const float*)d_in[0];
    const int*   types = (const int*)  d_in[1];
    const int*   rel   = (const int*)  d_in[2];
    const float* W_in  = (const float*)d_in[3];
    const float* b_in  = (const float*)d_in[4];
    const float* Wq    = (const float*)d_in[5];
    const float* Wk    = (const float*)d_in[6];
    const float* Wv    = (const float*)d_in[7];
    const float* Wo    = (const float*)d_in[8];
    const float* bq    = (const float*)d_in[9];
    const float* bk    = (const float*)d_in[10];
    const float* bv    = (const float*)d_in[11];
    const float* bo    = (const float*)d_in[12];
    const float* relp  = (const float*)d_in[13];
    const float* Wqkv  = (const float*)d_in[14];
    const float* bqkv  = (const float*)d_in[15];
    const float* Wot   = (const float*)d_in[16];
    const float* bot   = (const float*)d_in[17];
    const float* ln1_g = (const float*)d_in[18];
    const float* ln1_b = (const float*)d_in[19];
    const float* ln2_g = (const float*)d_in[20];
    const float* ln2_b = (const float*)d_in[21];
    const float* Wf1   = (const float*)d_in[22];
    const float* bf1   = (const float*)d_in[23];
    const float* Wf2   = (const float*)d_in[24];
    const float* bf2   = (const float*)d_in[25];
    const float* Wc    = (const float*)d_in[26];
    const float* bc    = (const float*)d_in[27];
    float* out = (float*)d_out;

    float *hA, *hB, *qkv, *tb, *wt, *bt;
    int *perm, *meta;
    cudaGetSymbolAddress((void**)&hA,   g_hA);
    cudaGetSymbolAddress((void**)&hB,   g_hB);
    cudaGetSymbolAddress((void**)&qkv,  g_qkv);
    cudaGetSymbolAddress((void**)&tb,   g_t);
    cudaGetSymbolAddress((void**)&wt,   g_wt);
    cudaGetSymbolAddress((void**)&bt,   g_bt);
    cudaGetSymbolAddress((void**)&perm, g_perm);
    cudaGetSymbolAddress((void**)&meta, g_meta);

    __nv_bfloat16 *xs, *hsA, *hsB, *msgs, *ffs, *lns;
    __nv_bfloat16 *binT, *qkvT, *woT, *encT, *wotT, *f1T, *f2T;
    cudaGetSymbolAddress((void**)&xs,   g_xs);
    cudaGetSymbolAddress((void**)&hsA,  g_hsA);
    cudaGetSymbolAddress((void**)&hsB,  g_hsB);
    cudaGetSymbolAddress((void**)&msgs, g_msgs);
    cudaGetSymbolAddress((void**)&ffs,  g_ffs);
    cudaGetSymbolAddress((void**)&lns,  g_lns);
    cudaGetSymbolAddress((void**)&binT, g_binT);
    cudaGetSymbolAddress((void**)&qkvT, g_qkvT);
    cudaGetSymbolAddress((void**)&woT,  g_woT);
    cudaGetSymbolAddress((void**)&encT, g_encT);
    cudaGetSymbolAddress((void**)&wotT, g_wotT);
    cudaGetSymbolAddress((void**)&f1T,  g_f1T);
    cudaGetSymbolAddress((void**)&f2T,  g_f2T);

    auto XH = xs;                 auto XL = xs + Mc * INc;
    auto HAH = hsA;               auto HAL = hsA + Mc * Dc;
    auto HBH = hsB;               auto HBL = hsB + Mc * Dc;
    auto MSH = msgs;              auto MSL = msgs + Mc * Dc;
    auto FFH = ffs;               auto FFL = ffs + (size_t)Mc * FFc;
    auto LNH = lns;               auto LNL = lns + Mc * Dc;
    auto BINH = binT;             auto BINL = binT + Dc * INc;
    auto ENCH = encT;             auto ENCL = encT + QS * Dc;
    auto WOTH = wotT;             auto WOTL = wotT + Dc * Dc;
    auto F1H = f1T;               auto F1L = f1T + FFc * Dc;
    auto F2H = f2T;               auto F2L = f2T + Dc * FFc;
    auto QT = [&](int tp, int hl) { return qkvT + ((size_t)tp * 2 + hl) * QS * Dc; };
    auto WT = [&](int tp, int hl) { return woT + ((size_t)tp * 2 + hl) * Dc * Dc; };

    const int ATTN_SMEM = (AR * SP + 32 * 36 + 128 * 36 + Nc) * 4;
    cudaFuncSetAttribute(attn2, cudaFuncAttributeMaxDynamicSharedMemorySize, ATTN_SMEM);
    cudaFuncSetAttribute(mm_bf, cudaFuncAttributeMaxDynamicSharedMemorySize, MMB_DYN);

    const dim3 thr(256);

    setup_perm<<<1, Nc>>>(types, perm, meta);
    fsplit<<<(Mc * INc + 255) / 256, thr>>>(x, XH, XL, Mc * INc);

    // weight transposes + splits
    tsplit<<<dim3(Dc / 32, INc / 32), thr>>>(W_in, INc, Dc, BINH, BINL);
    tsplit<<<dim3(QS / 32, Dc / 32), thr>>>(Wqkv, Dc, QS, ENCH, ENCL);
    tsplit<<<dim3(Dc / 32, Dc / 32), thr>>>(Wot, Dc, Dc, WOTH, WOTL);
    tsplit<<<dim3(FFc / 32, Dc / 32), thr>>>(Wf1, Dc, FFc, F1H, F1L);
    tsplit<<<dim3(Dc / 32, FFc / 32), thr>>>(Wf2, FFc, Dc, F2H, F2L);

    // input projection: hA (f32) + split
    mm_bf<<<dim3(2, 128), thr, MMB_DYN>>>(XH, XL, INc, Dc, BINH, BINL, nullptr, nullptr,
                                          b_in, nullptr, nullptr, nullptr,
                                          nullptr, hA, HAH, HAL, 0);

    float* hcur = hA;  float* hnext = hB;
    __nv_bfloat16 *hscH = HAH, *hscL = HAL, *hsnH = HBH, *hsnL = HBL;

    for (int l = 0; l < Lc; l++) {
        pack_w<<<(2 * Dc * QS + 255) / 256, thr>>>(Wq, Wk, Wv, l, wt);
        pack_b<<<(2 * QS + 255) / 256, thr>>>(bq, bk, bv, l, bt);
        tsplit<<<dim3(QS / 32, Dc / 32), thr>>>(wt, Dc, QS, QT(0, 0), QT(0, 1));
        tsplit<<<dim3(QS / 32, Dc / 32), thr>>>(wt + Dc * QS, Dc, QS, QT(1, 0), QT(1, 1));
        tsplit<<<dim3(Dc / 32, Dc / 32), thr>>>(Wo + (size_t)(l * 2 + 0) * Dc * Dc,
                                                Dc, Dc, WT(0, 0), WT(0, 1));
        tsplit<<<dim3(Dc / 32, Dc / 32), thr>>>(Wo + (size_t)(l * 2 + 1) * Dc * Dc,
                                                Dc, Dc, WT(1, 0), WT(1, 1));

        // typed QKV projection -> qkv f32
        mm_bf<<<dim3(6, 130), thr, MMB_DYN>>>(hscH, hscL, Dc, QS,
                                              QT(0, 0), QT(0, 1), QT(1, 0), QT(1, 1),
                                              bt, bt + QS, perm, meta,
                                              nullptr, qkv, nullptr, nullptr, 0);

        attn2<<<dim3(Nc / AR, Hc, Bc), thr, ATTN_SMEM>>>(
            qkv, MSH, MSL, relp + (size_t)l * Rc * Hc, rel, 1);

        // typed output projection + residual -> hnext f32 + split
        const float* bo0 = bo + (size_t)(l * 2 + 0) * Dc;
        const float* bo1 = bo + (size_t)(l * 2 + 1) * Dc;
        mm_bf<<<dim3(2, 130), thr, MMB_DYN>>>(MSH, MSL, Dc, Dc,
                                              WT(0, 0), WT(0, 1), WT(1, 0), WT(1, 1),
                                              bo0, bo1, perm, meta,
                                              hcur, hnext, hsnH, hsnL, 0);
        { float* tf = hcur; hcur = hnext; hnext = tf; }
        { auto th = hscH; hscH = hsnH; hsnH = th; }
        { auto tl = hscL; hscL = hsnL; hsnL = tl; }
    }

    // encoder
    mm_bf<<<dim3(6, 128), thr, MMB_DYN>>>(hscH, hscL, Dc, QS, ENCH, ENCL, nullptr, nullptr,
                                          bqkv, nullptr, nullptr, nullptr,
                                          nullptr, qkv, nullptr, nullptr, 0);

    attn2<<<dim3(Nc / AR, Hc, Bc), thr, ATTN_SMEM>>>(qkv, MSH, MSL, nullptr, nullptr, 0);

    mm_bf<<<dim3(2, 128), thr, MMB_DYN>>>(MSH, MSL, Dc, Dc, WOTH, WOTL, nullptr, nullptr,
                                          bot, nullptr, nullptr, nullptr,
                                          hcur, tb, nullptr, nullptr, 0);

    ln_kernel<<<Mc, thr>>>(tb, ln1_g, ln1_b, hnext, LNH, LNL);

    // FF1 -> split only (relu)
    mm_bf<<<dim3(16, 128), thr, MMB_DYN>>>(LNH, LNL, Dc, FFc, F1H, F1L, nullptr, nullptr,
                                           bf1, nullptr, nullptr, nullptr,
                                           nullptr, nullptr, FFH, FFL, 1);

    // FF2 + residual -> tb f32
    mm_bf<<<dim3(2, 128), thr, MMB_DYN>>>(FFH, FFL, FFc, Dc, F2H, F2L, nullptr, nullptr,
                                          bf2, nullptr, nullptr, nullptr,
                                          hnext, tb, nullptr, nullptr, 0);

    float* hfin = out + (size_t)Mc * Vc;
    ln_kernel<<<Mc, thr>>>(tb, ln2_g, ln2_b, hfin, nullptr, nullptr);

    cls_kernel<<<Mc / 8, thr>>>(hfin, Wc, bc, out);
}

// round 5
// speedup vs baseline: 3.0128x; 1.6687x over previous
#include <cuda_runtime.h>
#include <cuda_bf16.h>
#include <cstdint>
#include <math.h>

// Problem constants
constexpr int Bc  = 32;
constexpr int Nc  = 512;
constexpr int INc = 128;
constexpr int Dc  = 256;
constexpr int Hc  = 8;
constexpr int Lc  = 2;
constexpr int Rc  = 10;
constexpr int FFc = 2048;
constexpr int Vc  = 10;
constexpr int Mc  = Bc * Nc;        // 16384
constexpr int MPAD = Mc + 256;      // 16640 = 130*128
constexpr int QS  = 3 * Dc;         // 768

// -------- scratch (device globals) ----------
__device__ float g_hA[Mc * Dc];
__device__ float g_hB[Mc * Dc];
__device__ float g_qkv[Mc * QS];    // reused as 2x bf16 (hi|lo) qkv
__device__ float g_t[Mc * Dc];
__device__ float g_wt[2 * Dc * QS];
__device__ float g_bt[2 * QS];
__device__ int   g_perm[MPAD];
__device__ int   g_meta[4];
// bf16 hi/lo activation splits
__device__ __nv_bfloat16 g_xs[2][Mc * INc];
__device__ __nv_bfloat16 g_hsA[2][Mc * Dc];
__device__ __nv_bfloat16 g_hsB[2][Mc * Dc];
__device__ __nv_bfloat16 g_msgs[2][Mc * Dc];
__device__ __nv_bfloat16 g_ffs[2][(size_t)Mc * FFc];
__device__ __nv_bfloat16 g_lns[2][Mc * Dc];
// bf16 hi/lo transposed weights [N][K]
__device__ __nv_bfloat16 g_binT[2][Dc * INc];
__device__ __nv_bfloat16 g_qkvT[2][2][QS * Dc];   // [type][hi/lo]
__device__ __nv_bfloat16 g_woT[2][2][Dc * Dc];
__device__ __nv_bfloat16 g_encT[2][QS * Dc];
__device__ __nv_bfloat16 g_wotT[2][Dc * Dc];
__device__ __nv_bfloat16 g_f1T[2][FFc * Dc];
__device__ __nv_bfloat16 g_f2T[2][Dc * FFc];

// ---------------------------------------------------------------------------
// helpers
// ---------------------------------------------------------------------------
__device__ __forceinline__ uint32_t smem_u32(const void* p) {
    uint32_t a;
    asm("{ .reg .u64 t; cvta.to.shared.u64 t, %1; cvt.u32.u64 %0, t; }"
        : "=r"(a) : "l"(p));
    return a;
}
#define SWZ128(o) ((o) ^ (((o) >> 3) & 0x70))

#define CP_A16(sm, gm) \
    asm volatile("cp.async.cg.shared.global [%0], [%1], 16;" :: "r"(sm), "l"(gm))
#define CP_COMMIT() asm volatile("cp.async.commit_group;" ::: "memory")
#define CP_WAIT1()  asm volatile("cp.async.wait_group 1;" ::: "memory")
#define CP_WAIT0()  asm volatile("cp.async.wait_group 0;" ::: "memory")

#define LDSM4(r, addr) \
    asm volatile("ldmatrix.sync.aligned.m8n8.x4.shared.b16 {%0,%1,%2,%3}, [%4];" \
        : "=r"((r)[0]), "=r"((r)[1]), "=r"((r)[2]), "=r"((r)[3]) : "r"(addr))
#define LDSM4T(r, addr) \
    asm volatile("ldmatrix.sync.aligned.m8n8.x4.trans.shared.b16 {%0,%1,%2,%3}, [%4];" \
        : "=r"((r)[0]), "=r"((r)[1]), "=r"((r)[2]), "=r"((r)[3]) : "r"(addr))

#define MMA16816(d, a, b0_, b1_) \
    asm volatile("mma.sync.aligned.m16n8k16.row.col.f32.bf16.bf16.f32 " \
        "{%0,%1,%2,%3}, {%4,%5,%6,%7}, {%8,%9}, {%0,%1,%2,%3};" \
        : "+f"((d)[0]), "+f"((d)[1]), "+f"((d)[2]), "+f"((d)[3]) \
        : "r"((a)[0]), "r"((a)[1]), "r"((a)[2]), "r"((a)[3]), "r"(b0_), "r"(b1_))

__device__ __forceinline__ void split_bf(float v, __nv_bfloat16& h, __nv_bfloat16& l) {
    h = __float2bfloat16(v);
    l = __float2bfloat16(v - __bfloat162float(h));
}
// pack two floats into bf16x2 reg: lo -> low half, hi -> high half
__device__ __forceinline__ uint32_t pack2(float lo, float hi) {
    uint32_t d;
    asm("cvt.rn.bf16x2.f32 %0, %1, %2;" : "=r"(d) : "f"(hi), "f"(lo));
    return d;
}
__device__ __forceinline__ float lo_of(float p) {
    return p - __bfloat162float(__float2bfloat16(p));
}

// ---------------------------------------------------------------------------
// setup_perm: partition rows by node type
// ---------------------------------------------------------------------------
__global__ void setup_perm(const int* __restrict__ types,
                           int* __restrict__ perm, int* __restrict__ meta)
{
    __shared__ int s[Nc];
    int n = threadIdx.x;
    int tp = types[n];
    s[n] = (tp == 0) ? 1 : 0;
    __syncthreads();
    for (int off = 1; off < Nc; off <<= 1) {
        int v = s[n];
        int add = (n >= off) ? s[n - off] : 0;
        __syncthreads();
        s[n] = v + add;
        __syncthreads();
    }
    int count0 = s[Nc - 1];
    int rank = (tp == 0) ? (s[n] - 1) : (n - s[n]);
    int rows0  = count0 * Bc;
    int rows0p = (rows0 + 127) & ~127;
    int base = (tp == 0) ? rank * Bc : rows0p + rank * Bc;
    for (int b = 0; b < Bc; b++)
        perm[base + b] = b * Nc + n;
    if (n == 0) meta[0] = rows0p;
    __syncthreads();
    int rows1 = (Nc - count0) * Bc;
    int total = rows0p + rows1;
    for (int i = n; i < MPAD; i += Nc)
        if ((i >= rows0 && i < rows0p) || i >= total) perm[i] = -1;
}

// ---------------------------------------------------------------------------
// transpose + bf16-split: src fp32 [K][N] -> hi/lo bf16 [N][K]
// ---------------------------------------------------------------------------
__global__ __launch_bounds__(256)
void tsplit(const float* __restrict__ src, int K, int N,
            __nv_bfloat16* __restrict__ dhi, __nv_bfloat16* __restrict__ dlo)
{
    __shared__ float tile[32][33];
    int n0 = blockIdx.x * 32, k0 = blockIdx.y * 32;
    int tx = threadIdx.x & 31, ty = threadIdx.x >> 5;
#pragma unroll
    for (int i = 0; i < 4; i++)
        tile[ty + 8 * i][tx] = src[(size_t)(k0 + ty + 8 * i) * N + n0 + tx];
    __syncthreads();
#pragma unroll
    for (int i = 0; i < 4; i++) {
        int n = n0 + ty + 8 * i;
        int k = k0 + tx;
        float v = tile[tx][ty + 8 * i];
        __nv_bfloat16 h, l;
        split_bf(v, h, l);
        dhi[(size_t)n * K + k] = h;
        dlo[(size_t)n * K + k] = l;
    }
}

__global__ __launch_bounds__(256)
void fsplit(const float* __restrict__ src, __nv_bfloat16* __restrict__ hi,
            __nv_bfloat16* __restrict__ lo, int n)
{
    int i = blockIdx.x * 256 + threadIdx.x;
    if (i < n) {
        __nv_bfloat16 h, l;
        split_bf(src[i], h, l);
        hi[i] = h; lo[i] = l;
    }
}

__global__ void pack_w(const float* __restrict__ Wq, const float* __restrict__ Wk,
                       const float* __restrict__ Wv, int l, float* __restrict__ out)
{
    int idx = blockIdx.x * 256 + threadIdx.x;
    if (idx >= 2 * Dc * QS) return;
    int t2 = idx / (Dc * QS);
    int rem = idx % (Dc * QS);
    int k = rem / QS, j = rem % QS;
    const float* src = (j < Dc) ? Wq : ((j < 2 * Dc) ? Wk : Wv);
    int jj = j & (Dc - 1);
    out[idx] = src[(((size_t)l * 2 + t2) * Dc + k) * Dc + jj];
}
__global__ void pack_b(const float* __restrict__ bq, const float* __restrict__ bk,
                       const float* __restrict__ bv, int l, float* __restrict__ out)
{
    int idx = blockIdx.x * 256 + threadIdx.x;
    if (idx >= 2 * QS) return;
    int t2 = idx / QS, j = idx % QS;
    const float* src = (j < Dc) ? bq : ((j < 2 * Dc) ? bk : bv);
    int jj = j & (Dc - 1);
    out[idx] = src[((size_t)l * 2 + t2) * Dc + jj];
}

// ---------------------------------------------------------------------------
// bf16 mma.sync GEMM with 2-term split (K' = 3K)  [unchanged core from R4]
// ---------------------------------------------------------------------------
constexpr int STAGE_BYTES = 32768;
constexpr int MMB_DYN = 132 * 130 * 4;

__global__ __launch_bounds__(256)
void mm_bf(const __nv_bfloat16* __restrict__ Ahi, const __nv_bfloat16* __restrict__ Alo,
           int K, int N,
           const __nv_bfloat16* __restrict__ Bhi0, const __nv_bfloat16* __restrict__ Blo0,
           const __nv_bfloat16* __restrict__ Bhi1, const __nv_bfloat16* __restrict__ Blo1,
           const float* __restrict__ bias0, const float* __restrict__ bias1,
           const int* __restrict__ perm, const int* __restrict__ meta,
           const float* __restrict__ res, float* __restrict__ Cf,
           __nv_bfloat16* __restrict__ Chi, __nv_bfloat16* __restrict__ Clo,
           int do_relu)
{
    extern __shared__ char sb[];
    __shared__ int sPerm[128];

    const int t = threadIdx.x;
    const int m0 = blockIdx.y * 128, n0 = blockIdx.x * 128;
    const bool typed = (perm != nullptr);

    const __nv_bfloat16* Bhi = Bhi0;
    const __nv_bfloat16* Blo = Blo0;
    const float* bias = bias0;
    if (typed && m0 >= meta[0]) { Bhi = Bhi1; Blo = Blo1; bias = bias1; }

    if (t < 128) sPerm[t] = typed ? perm[m0 + t] : (m0 + t);
    __syncthreads();

    const int lr = t >> 1;
    int ag = sPerm[lr]; if (ag < 0) ag = 0;
    const __nv_bfloat16* pAhi = Ahi + (size_t)ag * K;
    const __nv_bfloat16* pAlo = Alo + (size_t)ag * K;
    const __nv_bfloat16* pBhi = Bhi + (size_t)(n0 + lr) * K;
    const __nv_bfloat16* pBlo = Blo + (size_t)(n0 + lr) * K;
    const uint32_t sbase = smem_u32(sb);
    uint32_t offA[4];
#pragma unroll
    for (int i = 0; i < 4; i++) {
        int c = (t & 1) * 4 + i;
        offA[i] = SWZ128((uint32_t)(lr * 128 + c * 16));
    }
    const int S = 3 * K / 64;

    auto issue_load = [&](int kc, int stg) {
        int kp = kc * 64;
        int s = kp / K, k0 = kp - s * K;
        const __nv_bfloat16* pa = (s == 1) ? pAlo : pAhi;
        const __nv_bfloat16* pb = (s == 2) ? pBlo : pBhi;
        uint32_t so = sbase + stg * STAGE_BYTES;
#pragma unroll
        for (int i = 0; i < 4; i++) {
            int c = (t & 1) * 4 + i;
            CP_A16(so + offA[i], pa + k0 + c * 8);
            CP_A16(so + 16384 + offA[i], pb + k0 + c * 8);
        }
        CP_COMMIT();
    };

    float acc[4][4][4] = {};
    const int wid = t >> 5, lane = t & 31;
    const int wm = wid & 1, wn = wid >> 1;

    issue_load(0, 0);
    issue_load(1, 1);

    for (int kc = 0; kc < S; kc++) {
        if (kc + 1 < S) { CP_WAIT1(); } else { CP_WAIT0(); }
        __syncthreads();
        uint32_t sA = sbase + (kc & 1) * STAGE_BYTES;
        uint32_t sB = sA + 16384;
#pragma unroll
        for (int kk = 0; kk < 64; kk += 16) {
            uint32_t a[4][4], b[2][4];
#pragma unroll
            for (int mi = 0; mi < 4; mi++) {
                int row = wm * 64 + mi * 16 + (lane & 15);
                int kcol = kk + ((lane >> 4) << 3);
                LDSM4(a[mi], sA + SWZ128((uint32_t)(row * 128 + kcol * 2)));
            }
#pragma unroll
            for (int bj = 0; bj < 2; bj++) {
                int nrow = wn * 32 + bj * 16 + ((lane >> 4) & 1) * 8 + (lane & 7);
                int kcol = kk + ((lane >> 3) & 1) * 8;
                LDSM4(b[bj], sB + SWZ128((uint32_t)(nrow * 128 + kcol * 2)));
            }
#pragma unroll
            for (int mi = 0; mi < 4; mi++)
#pragma unroll
                for (int bj = 0; bj < 2; bj++) {
                    MMA16816(acc[mi][bj * 2],     a[mi], b[bj][0], b[bj][1]);
                    MMA16816(acc[mi][bj * 2 + 1], a[mi], b[bj][2], b[bj][3]);
                }
        }
        __syncthreads();
        if (kc + 2 < S) issue_load(kc + 2, kc & 1);
    }

    float* Cs = (float*)sb;
#pragma unroll
    for (int mi = 0; mi < 4; mi++)
#pragma unroll
        for (int nj = 0; nj < 4; nj++) {
            int row = wm * 64 + mi * 16 + (lane >> 2);
            int col = wn * 32 + nj * 8 + (lane & 3) * 2;
            *reinterpret_cast<float2*>(&Cs[row * 130 + col]) =
                make_float2(acc[mi][nj][0], acc[mi][nj][1]);
            *reinterpret_cast<float2*>(&Cs[(row + 8) * 130 + col]) =
                make_float2(acc[mi][nj][2], acc[mi][nj][3]);
        }
    __syncthreads();

    {
        int col = t & 127, half = t >> 7;
        float bv = bias[n0 + col];
        for (int i = 0; i < 64; i++) {
            int r = half * 64 + i;
            int g = sPerm[r];
            if (g < 0) continue;
            float v = Cs[r * 130 + col] + bv;
            if (do_relu) v = fmaxf(v, 0.f);
            size_t o = (size_t)g * N + n0 + col;
            if (res) v += res[o];
            if (Cf) Cf[o] = v;
            if (Chi) {
                __nv_bfloat16 h, l;
                split_bf(v, h, l);
                Chi[o] = h; Clo[o] = l;
            }
        }
    }
}

// ---------------------------------------------------------------------------
// attn3: flash attention on tensor cores, bf16 2-term split (3 products).
// Block = (128 query rows, h, b); 8 warps, warp = 16 rows.
// qkv as bf16 hi/lo arrays (stride QS): Q at 0, K at Dc, V at 2*Dc.
// K/V chunks of 128 keys double-buffered via cp.async, row pitch 80B.
// ---------------------------------------------------------------------------
constexpr int FA_PITCH = 80;
constexpr int FA_Q_H = 0;
constexpr int FA_Q_L = 10240;
constexpr int FA_KV  = 20480;            // + buf*40960
constexpr int FA_KH = 0, FA_KL = 10240, FA_VH = 20480, FA_VL = 30720;
constexpr int FA_BIAS = FA_KV + 2 * 40960;   // 102400
constexpr int FA_SMEM = FA_BIAS + Nc * 4;    // 104448

__global__ __launch_bounds__(256)
void attn3(const __nv_bfloat16* __restrict__ qh, const __nv_bfloat16* __restrict__ ql,
           __nv_bfloat16* __restrict__ outh, __nv_bfloat16* __restrict__ outl,
           const float* __restrict__ relp, const int* __restrict__ rel_ids,
           int do_gelu)
{
    extern __shared__ char sm[];
    const uint32_t sb = smem_u32(sm);
    const int t = threadIdx.x, lane = t & 31, w = t >> 5;
    const int h = blockIdx.y, b = blockIdx.z;
    const int rowbase = b * Nc;
    const int q0 = blockIdx.x * 128;

    float* sBias = (float*)(sm + FA_BIAS);
    for (int i = t; i < Nc; i += 256)
        sBias[i] = relp ? relp[rel_ids[rowbase + i] * Hc + h] : 0.f;

    // stage Q hi/lo
#pragma unroll
    for (int i = 0; i < 2; i++) {
        int id = t + 256 * i;
        int r = id >> 2, ch = id & 3;
        size_t go = (size_t)(rowbase + q0 + r) * QS + h * 32 + ch * 8;
        CP_A16(sb + FA_Q_H + r * FA_PITCH + ch * 16, qh + go);
        CP_A16(sb + FA_Q_L + r * FA_PITCH + ch * 16, ql + go);
    }
    CP_COMMIT();

    auto load_kv = [&](int c, int buf) {
        uint32_t base = sb + FA_KV + buf * 40960;
        int kr0 = rowbase + c * 128;
#pragma unroll
        for (int m = 0; m < 4; m++) {
            const __nv_bfloat16* src = (m & 1) ? ql : qh;
            int coloff = ((m >> 1) ? 2 * Dc : Dc) + h * 32;
            uint32_t dst = base + ((m >> 1) ? ((m & 1) ? FA_VL : FA_VH)
                                            : ((m & 1) ? FA_KL : FA_KH));
#pragma unroll
            for (int i = 0; i < 2; i++) {
                int id = t + 256 * i;
                int r = id >> 2, ch = id & 3;
                CP_A16(dst + r * FA_PITCH + ch * 16,
                       src + (size_t)(kr0 + r) * QS + coloff + ch * 8);
            }
        }
        CP_COMMIT();
    };

    uint32_t qfh[2][4], qfl[2][4];
    float m_[2] = {-1e30f, -1e30f};
    float l_[2] = {0.f, 0.f};
    float oc[4][4] = {};

    load_kv(0, 0);
    load_kv(1, 1);

    for (int c = 0; c < 4; c++) {
        if (c < 3) { CP_WAIT1(); } else { CP_WAIT0(); }
        __syncthreads();
        if (c == 0) {
#pragma unroll
            for (int ks = 0; ks < 2; ks++) {
                uint32_t off = (uint32_t)(w * 16 + (lane & 15)) * FA_PITCH
                             + (ks * 16 + (lane >> 4) * 8) * 2;
                LDSM4(qfh[ks], sb + FA_Q_H + off);
                LDSM4(qfl[ks], sb + FA_Q_L + off);
            }
        }
        uint32_t kvb = sb + FA_KV + (c & 1) * 40960;

        // ---- scores ----
        float S[16][4];
#pragma unroll
        for (int j = 0; j < 16; j++) { S[j][0] = S[j][1] = S[j][2] = S[j][3] = 0.f; }
#pragma unroll
        for (int pj = 0; pj < 8; pj++) {
#pragma unroll
            for (int ks = 0; ks < 2; ks++) {
                uint32_t off = (uint32_t)(pj * 16 + ((lane >> 4) & 1) * 8 + (lane & 7)) * FA_PITCH
                             + (ks * 16 + ((lane >> 3) & 1) * 8) * 2;
                uint32_t kh[4], kl[4];
                LDSM4(kh, kvb + FA_KH + off);
                LDSM4(kl, kvb + FA_KL + off);
                MMA16816(S[2 * pj],     qfh[ks], kh[0], kh[1]);
                MMA16816(S[2 * pj + 1], qfh[ks], kh[2], kh[3]);
                MMA16816(S[2 * pj],     qfl[ks], kh[0], kh[1]);
                MMA16816(S[2 * pj + 1], qfl[ks], kh[2], kh[3]);
                MMA16816(S[2 * pj],     qfh[ks], kl[0], kl[1]);
                MMA16816(S[2 * pj + 1], qfh[ks], kl[2], kl[3]);
            }
        }

        // ---- online softmax ----
        const float scl = 0.17677669529663687f;
        float mc0 = -1e30f, mc1 = -1e30f;
#pragma unroll
        for (int j = 0; j < 16; j++) {
            float b0 = sBias[c * 128 + j * 8 + (lane & 3) * 2];
            float b1 = sBias[c * 128 + j * 8 + (lane & 3) * 2 + 1];
            S[j][0] = fmaf(S[j][0], scl, b0);
            S[j][1] = fmaf(S[j][1], scl, b1);
            S[j][2] = fmaf(S[j][2], scl, b0);
            S[j][3] = fmaf(S[j][3], scl, b1);
            mc0 = fmaxf(mc0, fmaxf(S[j][0], S[j][1]));
            mc1 = fmaxf(mc1, fmaxf(S[j][2], S[j][3]));
        }
#pragma unroll
        for (int o = 1; o <= 2; o <<= 1) {
            mc0 = fmaxf(mc0, __shfl_xor_sync(0xffffffffu, mc0, o));
            mc1 = fmaxf(mc1, __shfl_xor_sync(0xffffffffu, mc1, o));
        }
        float mn0 = fmaxf(m_[0], mc0), mn1 = fmaxf(m_[1], mc1);
        float al0 = __expf(m_[0] - mn0), al1 = __expf(m_[1] - mn1);
        m_[0] = mn0; m_[1] = mn1;
        float ps0 = 0.f, ps1 = 0.f;
#pragma unroll
        for (int j = 0; j < 16; j++) {
            S[j][0] = __expf(S[j][0] - mn0);
            S[j][1] = __expf(S[j][1] - mn0);
            S[j][2] = __expf(S[j][2] - mn1);
            S[j][3] = __expf(S[j][3] - mn1);
            ps0 += S[j][0] + S[j][1];
            ps1 += S[j][2] + S[j][3];
        }
#pragma unroll
        for (int o = 1; o <= 2; o <<= 1) {
            ps0 += __shfl_xor_sync(0xffffffffu, ps0, o);
            ps1 += __shfl_xor_sync(0xffffffffu, ps1, o);
        }
        l_[0] = l_[0] * al0 + ps0;
        l_[1] = l_[1] * al1 + ps1;
#pragma unroll
        for (int j = 0; j < 4; j++) {
            oc[j][0] *= al0; oc[j][1] *= al0;
            oc[j][2] *= al1; oc[j][3] *= al1;
        }

        // ---- P @ V ----
#pragma unroll
        for (int kt = 0; kt < 8; kt++) {
            float p0 = S[2 * kt][0],     p1 = S[2 * kt][1];
            float p2 = S[2 * kt][2],     p3 = S[2 * kt][3];
            float p4 = S[2 * kt + 1][0], p5 = S[2 * kt + 1][1];
            float p6 = S[2 * kt + 1][2], p7 = S[2 * kt + 1][3];
            uint32_t ah[4], al[4];
            ah[0] = pack2(p0, p1); ah[1] = pack2(p2, p3);
            ah[2] = pack2(p4, p5); ah[3] = pack2(p6, p7);
            al[0] = pack2(lo_of(p0), lo_of(p1));
            al[1] = pack2(lo_of(p2), lo_of(p3));
            al[2] = pack2(lo_of(p4), lo_of(p5));
            al[3] = pack2(lo_of(p6), lo_of(p7));

            uint32_t voff = (uint32_t)(16 * kt + ((lane >> 3) & 1) * 8 + (lane & 7)) * FA_PITCH
                          + ((lane >> 4) * 8) * 2;
            uint32_t vh01[4], vh23[4], vl01[4], vl23[4];
            LDSM4T(vh01, kvb + FA_VH + voff);
            LDSM4T(vh23, kvb + FA_VH + voff + 32);
            LDSM4T(vl01, kvb + FA_VL + voff);
            LDSM4T(vl23, kvb + FA_VL + voff + 32);

            MMA16816(oc[0], ah, vh01[0], vh01[1]);
            MMA16816(oc[1], ah, vh01[2], vh01[3]);
            MMA16816(oc[2], ah, vh23[0], vh23[1]);
            MMA16816(oc[3], ah, vh23[2], vh23[3]);
            MMA16816(oc[0], al, vh01[0], vh01[1]);
            MMA16816(oc[1], al, vh01[2], vh01[3]);
            MMA16816(oc[2], al, vh23[0], vh23[1]);
            MMA16816(oc[3], al, vh23[2], vh23[3]);
            MMA16816(oc[0], ah, vl01[0], vl01[1]);
            MMA16816(oc[1], ah, vl01[2], vl01[3]);
            MMA16816(oc[2], ah, vl23[0], vl23[1]);
            MMA16816(oc[3], ah, vl23[2], vl23[3]);
        }

        __syncthreads();
        if (c + 2 < 4) load_kv(c + 2, c & 1);
    }

    // ---- epilogue ----
    float inv0 = 1.f / l_[0], inv1 = 1.f / l_[1];
    int row0 = rowbase + q0 + w * 16 + (lane >> 2);
    int row1 = row0 + 8;
#pragma unroll
    for (int j = 0; j < 4; j++) {
        float v[4] = {oc[j][0] * inv0, oc[j][1] * inv0,
                      oc[j][2] * inv1, oc[j][3] * inv1};
        if (do_gelu) {
#pragma unroll
            for (int i = 0; i < 4; i++) {
                float x = v[i];
                float cc = 0.7978845608028654f * (x + 0.044715f * x * x * x);
                v[i] = 0.5f * x * (1.f + tanhf(cc));
            }
        }
        __nv_bfloat16 h0, l0, h1, l1, h2, l2, h3, l3;
        split_bf(v[0], h0, l0); split_bf(v[1], h1, l1);
        split_bf(v[2], h2, l2); split_bf(v[3], h3, l3);
        int col = h * 32 + j * 8 + (lane & 3) * 2;
        __nv_bfloat162 ph0; ph0.x = h0; ph0.y = h1;
        __nv_bfloat162 pl0; pl0.x = l0; pl0.y = l1;
        __nv_bfloat162 ph1; ph1.x = h2; ph1.y = h3;
        __nv_bfloat162 pl1; pl1.x = l2; pl1.y = l3;
        *reinterpret_cast<uint32_t*>(outh + (size_t)row0 * Dc + col) =
            *reinterpret_cast<uint32_t*>(&ph0);
        *reinterpret_cast<uint32_t*>(outl + (size_t)row0 * Dc + col) =
            *reinterpret_cast<uint32_t*>(&pl0);
        *reinterpret_cast<uint32_t*>(outh + (size_t)row1 * Dc + col) =
            *reinterpret_cast<uint32_t*>(&ph1);
        *reinterpret_cast<uint32_t*>(outl + (size_t)row1 * Dc + col) =
            *reinterpret_cast<uint32_t*>(&pl1);
    }
}

// ---------------------------------------------------------------------------
// LayerNorm, optional bf16 split output
// ---------------------------------------------------------------------------
__global__ __launch_bounds__(256)
void ln_kernel(const float* __restrict__ x, const float* __restrict__ gg,
               const float* __restrict__ bb, float* __restrict__ out,
               __nv_bfloat16* __restrict__ ohi, __nv_bfloat16* __restrict__ olo)
{
    int row = blockIdx.x;
    int t = threadIdx.x;
    float v = x[(size_t)row * Dc + t];
    __shared__ float red[8];

    float s = v;
#pragma unroll
    for (int o = 16; o >= 1; o >>= 1) s += __shfl_xor_sync(0xffffffffu, s, o);
    if ((t & 31) == 0) red[t >> 5] = s;
    __syncthreads();
    float tot = 0.f;
#pragma unroll
    for (int i = 0; i < 8; i++) tot += red[i];
    float mean = tot * (1.f / 256.f);
    __syncthreads();

    float d = v - mean;
    s = d * d;
#pragma unroll
    for (int o = 16; o >= 1; o >>= 1) s += __shfl_xor_sync(0xffffffffu, s, o);
    if ((t & 31) == 0) red[t >> 5] = s;
    __syncthreads();
    tot = 0.f;
#pragma unroll
    for (int i = 0; i < 8; i++) tot += red[i];
    float var = tot * (1.f / 256.f);

    float r = d * rsqrtf(var + 1e-5f) * gg[t] + bb[t];
    out[(size_t)row * Dc + t] = r;
    if (ohi) {
        __nv_bfloat16 h, l;
        split_bf(r, h, l);
        ohi[(size_t)row * Dc + t] = h;
        olo[(size_t)row * Dc + t] = l;
    }
}

// ---------------------------------------------------------------------------
// Classifier (warp per row)
// ---------------------------------------------------------------------------
__global__ __launch_bounds__(256)
void cls_kernel(const float* __restrict__ h, const float* __restrict__ Wc,
                const float* __restrict__ bc, float* __restrict__ out)
{
    __shared__ float sW[Dc * Vc];
    __shared__ float sb[Vc];
    int t = threadIdx.x;
#pragma unroll
    for (int i = 0; i < 10; i++) {
        int idx = t + 256 * i;
        if (idx < Dc * Vc) sW[idx] = Wc[idx];
    }
    if (t < Vc) sb[t] = bc[t];
    __syncthreads();

    int wid = t >> 5, lane = t & 31;
    int row = blockIdx.x * 8 + wid;
    float hv[8];
#pragma unroll
    for (int j = 0; j < 8; j++) hv[j] = h[(size_t)row * Dc + lane + 32 * j];

    float sums[Vc];
#pragma unroll
    for (int v = 0; v < Vc; v++) {
        float p = 0.f;
#pragma unroll
        for (int j = 0; j < 8; j++) p += hv[j] * sW[(lane + 32 * j) * Vc + v];
#pragma unroll
        for (int o = 16; o >= 1; o >>= 1) p += __shfl_xor_sync(0xffffffffu, p, o);
        sums[v] = p;
    }
    if (lane == 0) {
#pragma unroll
        for (int v = 0; v < Vc; v++) out[(size_t)row * Vc + v] = sums[v] + sb[v];
    }
}

// ---------------------------------------------------------------------------
// Host orchestration
// ---------------------------------------------------------------------------
extern "C" void kernel_launch(void* const* d_in, const int* in_sizes, int n_in,
                              void* d_out, int out_size)
{
    (void)in_sizes; (void)n_in; (void)out_size;

    const float* x     = (const float*)d_in[0];
    const int*   types = (const int*)  d_in[1];
    const int*   rel   = (const int*)  d_in[2];
    const float* W_in  = (const float*)d_in[3];
    const float* b_in  = (const float*)d_in[4];
    const float* Wq    = (const float*)d_in[5];
    const float* Wk    = (const float*)d_in[6];
    const float* Wv    = (const float*)d_in[7];
    const float* Wo    = (const float*)d_in[8];
    const float* bq    = (const float*)d_in[9];
    const float* bk    = (const float*)d_in[10];
    const float* bv    = (const float*)d_in[11];
    const float* bo    = (const float*)d_in[12];
    const float* relp  = (const float*)d_in[13];
    const float* Wqkv  = (const float*)d_in[14];
    const float* bqkv  = (const float*)d_in[15];
    const float* Wot   = (const float*)d_in[16];
    const float* bot   = (const float*)d_in[17];
    const float* ln1_g = (const float*)d_in[18];
    const float* ln1_b = (const float*)d_in[19];
    const float* ln2_g = (const float*)d_in[20];
    const float* ln2_b = (const float*)d_in[21];
    const float* Wf1   = (const float*)d_in[22];
    const float* bf1   = (const float*)d_in[23];
    const float* Wf2   = (const float*)d_in[24];
    const float* bf2   = (const float*)d_in[25];
    const float* Wc    = (const float*)d_in[26];
    const float* bc    = (const float*)d_in[27];
    float* out = (float*)d_out;

    float *hA, *hB, *qkvf, *tb, *wt, *bt;
    int *perm, *meta;
    cudaGetSymbolAddress((void**)&hA,   g_hA);
    cudaGetSymbolAddress((void**)&hB,   g_hB);
    cudaGetSymbolAddress((void**)&qkvf, g_qkv);
    cudaGetSymbolAddress((void**)&tb,   g_t);
    cudaGetSymbolAddress((void**)&wt,   g_wt);
    cudaGetSymbolAddress((void**)&bt,   g_bt);
    cudaGetSymbolAddress((void**)&perm, g_perm);
    cudaGetSymbolAddress((void**)&meta, g_meta);

    __nv_bfloat16 *xs, *hsA, *hsB, *msgs, *ffs, *lns;
    __nv_bfloat16 *binT, *qkvT, *woT, *encT, *wotT, *f1T, *f2T;
    cudaGetSymbolAddress((void**)&xs,   g_xs);
    cudaGetSymbolAddress((void**)&hsA,  g_hsA);
    cudaGetSymbolAddress((void**)&hsB,  g_hsB);
    cudaGetSymbolAddress((void**)&msgs, g_msgs);
    cudaGetSymbolAddress((void**)&ffs,  g_ffs);
    cudaGetSymbolAddress((void**)&lns,  g_lns);
    cudaGetSymbolAddress((void**)&binT, g_binT);
    cudaGetSymbolAddress((void**)&qkvT, g_qkvT);
    cudaGetSymbolAddress((void**)&woT,  g_woT);
    cudaGetSymbolAddress((void**)&encT, g_encT);
    cudaGetSymbolAddress((void**)&wotT, g_wotT);
    cudaGetSymbolAddress((void**)&f1T,  g_f1T);
    cudaGetSymbolAddress((void**)&f2T,  g_f2T);

    __nv_bfloat16* qkvH = (__nv_bfloat16*)qkvf;
    __nv_bfloat16* qkvL = qkvH + (size_t)Mc * QS;

    auto XH = xs;                 auto XL = xs + Mc * INc;
    auto HAH = hsA;               auto HAL = hsA + Mc * Dc;
    auto HBH = hsB;               auto HBL = hsB + Mc * Dc;
    auto MSH = msgs;              auto MSL = msgs + Mc * Dc;
    auto FFH = ffs;               auto FFL = ffs + (size_t)Mc * FFc;
    auto LNH = lns;               auto LNL = lns + Mc * Dc;
    auto BINH = binT;             auto BINL = binT + Dc * INc;
    auto ENCH = encT;             auto ENCL = encT + QS * Dc;
    auto WOTH = wotT;             auto WOTL = wotT + Dc * Dc;
    auto F1H = f1T;               auto F1L = f1T + FFc * Dc;
    auto F2H = f2T;               auto F2L = f2T + Dc * FFc;
    auto QT = [&](int tp, int hl) { return qkvT + ((size_t)tp * 2 + hl) * QS * Dc; };
    auto WT = [&](int tp, int hl) { return woT + ((size_t)tp * 2 + hl) * Dc * Dc; };

    cudaFuncSetAttribute(mm_bf, cudaFuncAttributeMaxDynamicSharedMemorySize, MMB_DYN);
    cudaFuncSetAttribute(attn3, cudaFuncAttributeMaxDynamicSharedMemorySize, FA_SMEM);

    const dim3 thr(256);
    const dim3 fagrid(Nc / 128, Hc, Bc);

    // launches ordered so ncu (-s 5) profiles the first mm_bf
    setup_perm<<<1, Nc>>>(types, perm, meta);                                 // 0
    fsplit<<<(Mc * INc + 255) / 256, thr>>>(x, XH, XL, Mc * INc);             // 1
    tsplit<<<dim3(Dc / 32, INc / 32), thr>>>(W_in, INc, Dc, BINH, BINL);      // 2
    tsplit<<<dim3(FFc / 32, Dc / 32), thr>>>(Wf1, Dc, FFc, F1H, F1L);         // 3
    tsplit<<<dim3(Dc / 32, FFc / 32), thr>>>(Wf2, FFc, Dc, F2H, F2L);         // 4
    // input projection: hA (f32) + split                                      // 5
    mm_bf<<<dim3(2, 128), thr, MMB_DYN>>>(XH, XL, INc, Dc, BINH, BINL, nullptr, nullptr,
                                          b_in, nullptr, nullptr, nullptr,
                                          nullptr, hA, HAH, HAL, 0);
    tsplit<<<dim3(QS / 32, Dc / 32), thr>>>(Wqkv, Dc, QS, ENCH, ENCL);
    tsplit<<<dim3(Dc / 32, Dc / 32), thr>>>(Wot, Dc, Dc, WOTH, WOTL);

    float* hcur = hA;  float* hnext = hB;
    __nv_bfloat16 *hscH = HAH, *hscL = HAL, *hsnH = HBH, *hsnL = HBL;

    for (int l = 0; l < Lc; l++) {
        pack_w<<<(2 * Dc * QS + 255) / 256, thr>>>(Wq, Wk, Wv, l, wt);
        pack_b<<<(2 * QS + 255) / 256, thr>>>(bq, bk, bv, l, bt);
        tsplit<<<dim3(QS / 32, Dc / 32), thr>>>(wt, Dc, QS, QT(0, 0), QT(0, 1));
        tsplit<<<dim3(QS / 32, Dc / 32), thr>>>(wt + Dc * QS, Dc, QS, QT(1, 0), QT(1, 1));
        tsplit<<<dim3(Dc / 32, Dc / 32), thr>>>(Wo + (size_t)(l * 2 + 0) * Dc * Dc,
                                                Dc, Dc, WT(0, 0), WT(0, 1));
        tsplit<<<dim3(Dc / 32, Dc / 32), thr>>>(Wo + (size_t)(l * 2 + 1) * Dc * Dc,
                                                Dc, Dc, WT(1, 0), WT(1, 1));

        // typed QKV projection -> split bf16 qkv
        mm_bf<<<dim3(6, 130), thr, MMB_DYN>>>(hscH, hscL, Dc, QS,
                                              QT(0, 0), QT(0, 1), QT(1, 0), QT(1, 1),
                                              bt, bt + QS, perm, meta,
                                              nullptr, nullptr, qkvH, qkvL, 0);

        attn3<<<fagrid, thr, FA_SMEM>>>(qkvH, qkvL, MSH, MSL,
                                        relp + (size_t)l * Rc * Hc, rel, 1);

        const float* bo0 = bo + (size_t)(l * 2 + 0) * Dc;
        const float* bo1 = bo + (size_t)(l * 2 + 1) * Dc;
        mm_bf<<<dim3(2, 130), thr, MMB_DYN>>>(MSH, MSL, Dc, Dc,
                                              WT(0, 0), WT(0, 1), WT(1, 0), WT(1, 1),
                                              bo0, bo1, perm, meta,
                                              hcur, hnext, hsnH, hsnL, 0);
        { float* tf = hcur; hcur = hnext; hnext = tf; }
        { auto th = hscH; hscH = hsnH; hsnH = th; }
        { auto tl = hscL; hscL = hsnL; hsnL = tl; }
    }

    // encoder
    mm_bf<<<dim3(6, 128), thr, MMB_DYN>>>(hscH, hscL, Dc, QS, ENCH, ENCL, nullptr, nullptr,
                                          bqkv, nullptr, nullptr, nullptr,
                                          nullptr, nullptr, qkvH, qkvL, 0);

    attn3<<<fagrid, thr, FA_SMEM>>>(qkvH, qkvL, MSH, MSL, nullptr, nullptr, 0);

    mm_bf<<<dim3(2, 128), thr, MMB_DYN>>>(MSH, MSL, Dc, Dc, WOTH, WOTL, nullptr, nullptr,
                                          bot, nullptr, nullptr, nullptr,
                                          hcur, tb, nullptr, nullptr, 0);

    ln_kernel<<<Mc, thr>>>(tb, ln1_g, ln1_b, hnext, LNH, LNL);

    mm_bf<<<dim3(16, 128), thr, MMB_DYN>>>(LNH, LNL, Dc, FFc, F1H, F1L, nullptr, nullptr,
                                           bf1, nullptr, nullptr, nullptr,
                                           nullptr, nullptr, FFH, FFL, 1);

    mm_bf<<<dim3(2, 128), thr, MMB_DYN>>>(FFH, FFL, FFc, Dc, F2H, F2L, nullptr, nullptr,
                                          bf2, nullptr, nullptr, nullptr,
                                          hnext, tb, nullptr, nullptr, 0);

    float* hfin = out + (size_t)Mc * Vc;
    ln_kernel<<<Mc, thr>>>(tb, ln2_g, ln2_b, hfin, nullptr, nullptr);

    cls_kernel<<<Mc / 8, thr>>>(hfin, Wc, bc, out);
}